// round 2
// baseline (speedup 1.0000x reference)
#include <cuda_runtime.h>

#define BB 4
#define LL 4096
#define DD 1024
#define HH 16
#define HD 64
#define MM 256
#define NSPLIT 8
#define LSPL (LL/NSPLIT)
#define CH 32

#define SCALE 0.17677669529663689f   /* 1024^-0.25 */
#define CF    0.0625f                /* 256^-0.5   */
#define EPSV  1e-4f
#define CEPS  (0.0625f*1e-4f)

__device__ float    g_kv[BB*HH*MM*HD];   // 4 MB scratch
__device__ float    g_ksum[BB*HH*MM];
__device__ unsigned g_minbits;

// FMA-pipe exp: exp(x) = 2^(x*log2e), magic-constant split + degree-6 poly.
__device__ __forceinline__ float fexp(float x) {
    float t = x * 1.4426950408889634f;
    t = fminf(fmaxf(t, -126.0f), 126.0f);
    float z = t + 12582912.0f;                 // 1.5 * 2^23
    int   n = __float_as_int(z) - 0x4B400000;  // round(t)
    float f = t - (float)n;                    // |f| <= 0.5
    float p = 1.54035304e-4f;
    p = fmaf(p, f, 1.33335581e-3f);
    p = fmaf(p, f, 9.61812911e-3f);
    p = fmaf(p, f, 5.55041087e-2f);
    p = fmaf(p, f, 2.40226507e-1f);
    p = fmaf(p, f, 6.93147181e-1f);
    p = fmaf(p, f, 1.0f);
    return __int_as_float((n + 127) << 23) * p;
}

// ---------------- Kernel 1: global min of ||k_scaled||^2 per head-row -------
__global__ void __launch_bounds__(256) k_minsq(const float* __restrict__ Kt) {
    int idx = blockIdx.x * 256 + threadIdx.x;   // one head-row (64 floats) each
    const float4* p = (const float4*)Kt + (size_t)idx * 16;
    float s = 0.f;
#pragma unroll
    for (int i = 0; i < 16; i++) {
        float4 v = p[i];
        s = fmaf(v.x, v.x, s); s = fmaf(v.y, v.y, s);
        s = fmaf(v.z, v.z, s); s = fmaf(v.w, v.w, s);
    }
    s *= SCALE * SCALE;
#pragma unroll
    for (int o = 16; o; o >>= 1) s = fminf(s, __shfl_xor_sync(0xffffffffu, s, o));
    if ((threadIdx.x & 31) == 0) atomicMin(&g_minbits, __float_as_uint(s));
}

// ---------------- Kernel 2: k' = phi(k); accumulate kv = k'^T v, ksum -------
__global__ void __launch_bounds__(256)
k_kv(const float* __restrict__ Kt, const float* __restrict__ Vt,
     const float* __restrict__ Wt) {
    extern __shared__ float sm[];
    float* W_s  = sm;                 // 256*65
    float* k_s  = W_s + 256 * 65;     // 32*65
    float* v_s  = k_s + 32 * 65;      // 32*68
    float* kp_s = v_s + 32 * 68;      // 256*33  (layout [m][l])
    float* h_s  = kp_s + 256 * 33;    // 32

    const int tid = threadIdx.x;
    const int bh  = blockIdx.x >> 3;
    const int spl = blockIdx.x & 7;
    const int b = bh >> 4, hh = bh & 15;
    const float stab = -0.5f * __uint_as_float(g_minbits);

    // Load full W into smem, [m][kk] stride 65 (conflict-free in proj)
    for (int i = tid; i < 256 * 16; i += 256) {
        int mm = i >> 4, c4 = (i & 15) * 4;
        float4 w4 = ((const float4*)Wt)[i];
        float* d = &W_s[mm * 65 + c4];
        d[0] = w4.x; d[1] = w4.y; d[2] = w4.z; d[3] = w4.w;
    }

    float acc[8][8];
#pragma unroll
    for (int a = 0; a < 8; a++)
#pragma unroll
        for (int c = 0; c < 8; c++) acc[a][c] = 0.f;
    float ksum[8] = {0, 0, 0, 0, 0, 0, 0, 0};

    const int tm = tid >> 3, td = tid & 7;
    const int l0 = spl * LSPL;
    const float* Kb = Kt + ((size_t)b * LL) * DD + hh * HD;
    const float* Vb = Vt + ((size_t)b * LL) * DD + hh * HD;
    __syncthreads();

    for (int c0 = 0; c0 < LSPL; c0 += CH) {
        // load k chunk (scaled) + v chunk
        for (int i = tid; i < CH * 16; i += 256) {
            int r = i >> 4, c4 = (i & 15) * 4;
            float4 k4 = *(const float4*)(Kb + (size_t)(l0 + c0 + r) * DD + c4);
            float* dk = &k_s[r * 65 + c4];
            dk[0] = k4.x * SCALE; dk[1] = k4.y * SCALE;
            dk[2] = k4.z * SCALE; dk[3] = k4.w * SCALE;
            float4 v4 = *(const float4*)(Vb + (size_t)(l0 + c0 + r) * DD + c4);
            *(float4*)(&v_s[r * 68 + c4]) = v4;
        }
        __syncthreads();
        if (tid < CH) {
            float s = 0.f;
#pragma unroll
            for (int kk = 0; kk < 64; kk++) { float x = k_s[tid * 65 + kk]; s = fmaf(x, x, s); }
            h_s[tid] = -0.5f * s;
        }
        __syncthreads();
        // proj [32 l, 256 m] + phi -> kp_s[m][l]
        {
            const int lg = tid & 7, mg = tid >> 3;  // 4 l x 8 m per thread
            float pr[4][8];
#pragma unroll
            for (int i = 0; i < 4; i++)
#pragma unroll
                for (int j = 0; j < 8; j++) pr[i][j] = 0.f;
#pragma unroll 4
            for (int kk = 0; kk < 64; kk++) {
                float a[4];
#pragma unroll
                for (int i = 0; i < 4; i++) a[i] = k_s[(lg * 4 + i) * 65 + kk];
#pragma unroll
                for (int j = 0; j < 8; j++) {
                    float w = W_s[(mg * 8 + j) * 65 + kk];
#pragma unroll
                    for (int i = 0; i < 4; i++) pr[i][j] = fmaf(a[i], w, pr[i][j]);
                }
            }
#pragma unroll
            for (int i = 0; i < 4; i++) {
                float hb = h_s[lg * 4 + i] - stab;
#pragma unroll
                for (int j = 0; j < 8; j++) {
                    float ker = fexp(hb + pr[i][j]);
                    kp_s[(mg * 8 + j) * 33 + lg * 4 + i] = fmaf(CF, ker, CEPS);
                }
            }
        }
        __syncthreads();
        // accumulate kv[256,64] += kp[256,32] @ v[32,64]
#pragma unroll 2
        for (int ll = 0; ll < CH; ll++) {
            float a[8];
#pragma unroll
            for (int jm = 0; jm < 8; jm++) a[jm] = kp_s[(tm * 8 + jm) * 33 + ll];
            float4 b0 = *(const float4*)&v_s[ll * 68 + td * 8];
            float4 b1 = *(const float4*)&v_s[ll * 68 + td * 8 + 4];
            float bb[8] = {b0.x, b0.y, b0.z, b0.w, b1.x, b1.y, b1.z, b1.w};
            if (td == 0) {
#pragma unroll
                for (int jm = 0; jm < 8; jm++) ksum[jm] += a[jm];
            }
#pragma unroll
            for (int jm = 0; jm < 8; jm++)
#pragma unroll
                for (int jd = 0; jd < 8; jd++)
                    acc[jm][jd] = fmaf(a[jm], bb[jd], acc[jm][jd]);
        }
        __syncthreads();
    }
    float* kvg = g_kv + (size_t)bh * MM * HD;
#pragma unroll
    for (int jm = 0; jm < 8; jm++)
#pragma unroll
        for (int jd = 0; jd < 8; jd++)
            atomicAdd(&kvg[(tm * 8 + jm) * HD + td * 8 + jd], acc[jm][jd]);
    if (td == 0) {
#pragma unroll
        for (int jm = 0; jm < 8; jm++)
            atomicAdd(&g_ksum[bh * MM + tm * 8 + jm], ksum[jm]);
    }
}

// ---------------- Kernel 3: q' = phi(q); out = (q' @ kv) / (q' . ksum) ------
__global__ void __launch_bounds__(256)
k_out(const float* __restrict__ Qt, const float* __restrict__ Wt,
      float* __restrict__ Out) {
    extern __shared__ float sm[];
    float* q_s   = sm;                 // 128*65
    float* Wc_s  = q_s + 128 * 65;     // 32*65
    float* kvc_s = Wc_s + 32 * 65;     // 32*68
    float* qp_s  = kvc_s + 32 * 68;    // 128*33
    float* ks_s  = qp_s + 128 * 33;    // 32

    const int tid = threadIdx.x;
    const int bh  = blockIdx.x >> 5;
    const int lc  = blockIdx.x & 31;
    const int b = bh >> 4, hh = bh & 15;
    const int l0 = lc * 128;
    const float* Qb = Qt + ((size_t)b * LL + l0) * DD + hh * HD;

    for (int i = tid; i < 128 * 16; i += 256) {
        int r = i >> 4, c4 = (i & 15) * 4;
        float4 q4 = *(const float4*)(Qb + (size_t)r * DD + c4);
        float* dq = &q_s[r * 65 + c4];
        dq[0] = q4.x * SCALE; dq[1] = q4.y * SCALE;
        dq[2] = q4.z * SCALE; dq[3] = q4.w * SCALE;
    }

    float acc[4][8];
#pragma unroll
    for (int i = 0; i < 4; i++)
#pragma unroll
        for (int j = 0; j < 8; j++) acc[i][j] = 0.f;
    float den[4] = {0, 0, 0, 0};

    const int lgo = tid >> 3, td = tid & 7;   // out tile: 4 l x 8 d
    const float* kvg = g_kv + (size_t)bh * MM * HD;
    const float* ksg = g_ksum + bh * MM;

    for (int mc = 0; mc < MM; mc += 32) {
        __syncthreads();   // prev GEMM done before overwriting tiles (also orders q_s load)
        for (int i = tid; i < 32 * 16; i += 256) {
            int r = i >> 4, c4 = (i & 15) * 4;
            float4 w4 = ((const float4*)Wt)[(mc + r) * 16 + (i & 15)];
            float* dw = &Wc_s[r * 65 + c4];
            dw[0] = w4.x; dw[1] = w4.y; dw[2] = w4.z; dw[3] = w4.w;
            float4 kv4 = *(const float4*)(kvg + (size_t)(mc + r) * HD + c4);
            *(float4*)&kvc_s[r * 68 + c4] = kv4;
        }
        if (tid < 32) ks_s[tid] = ksg[mc + tid];
        __syncthreads();
        // proj [128 l, 32 m]: thread = 4 l x 4 m
        {
            const int mg = tid & 7, lg = tid >> 3;
            float pr[4][4];
#pragma unroll
            for (int i = 0; i < 4; i++)
#pragma unroll
                for (int j = 0; j < 4; j++) pr[i][j] = 0.f;
#pragma unroll 4
            for (int kk = 0; kk < 64; kk++) {
                float a[4];
#pragma unroll
                for (int i = 0; i < 4; i++) a[i] = q_s[(lg * 4 + i) * 65 + kk];
#pragma unroll
                for (int j = 0; j < 4; j++) {
                    float w = Wc_s[(mg * 4 + j) * 65 + kk];
#pragma unroll
                    for (int i = 0; i < 4; i++) pr[i][j] = fmaf(a[i], w, pr[i][j]);
                }
            }
#pragma unroll
            for (int i = 0; i < 4; i++)
#pragma unroll
                for (int j = 0; j < 4; j++)
                    qp_s[(lg * 4 + i) * 33 + mg * 4 + j] = fmaf(CF, fexp(pr[i][j]), CEPS);
        }
        __syncthreads();
#pragma unroll 2
        for (int mmi = 0; mmi < 32; mmi++) {
            float aa[4];
#pragma unroll
            for (int i = 0; i < 4; i++) aa[i] = qp_s[(lgo * 4 + i) * 33 + mmi];
            float4 b0 = *(const float4*)&kvc_s[mmi * 68 + td * 8];
            float4 b1 = *(const float4*)&kvc_s[mmi * 68 + td * 8 + 4];
            float bb[8] = {b0.x, b0.y, b0.z, b0.w, b1.x, b1.y, b1.z, b1.w};
            float ks = ks_s[mmi];
#pragma unroll
            for (int i = 0; i < 4; i++) den[i] = fmaf(aa[i], ks, den[i]);
#pragma unroll
            for (int i = 0; i < 4; i++)
#pragma unroll
                for (int jd = 0; jd < 8; jd++)
                    acc[i][jd] = fmaf(aa[i], bb[jd], acc[i][jd]);
        }
    }

    float* Ob = Out + ((size_t)b * LL + l0) * DD + hh * HD;
#pragma unroll
    for (int i = 0; i < 4; i++) {
        float dd = den[i];
        if (fabsf(dd) <= EPSV) dd += 2.f * EPSV;
        float inv = 1.0f / dd;
        int l = lgo * 4 + i;
        float4 o0 = make_float4(acc[i][0] * inv, acc[i][1] * inv,
                                acc[i][2] * inv, acc[i][3] * inv);
        float4 o1 = make_float4(acc[i][4] * inv, acc[i][5] * inv,
                                acc[i][6] * inv, acc[i][7] * inv);
        *(float4*)(Ob + (size_t)l * DD + td * 8) = o0;
        *(float4*)(Ob + (size_t)l * DD + td * 8 + 4) = o1;
    }
}

extern "C" void kernel_launch(void* const* d_in, const int* in_sizes, int n_in,
                              void* d_out, int out_size) {
    const float* q = (const float*)d_in[0];
    const float* k = (const float*)d_in[1];
    const float* v = (const float*)d_in[2];
    const float* W = (const float*)d_in[3];
    float* out = (float*)d_out;

    void *pkv, *pks, *pmin;
    cudaGetSymbolAddress(&pkv, g_kv);
    cudaGetSymbolAddress(&pks, g_ksum);
    cudaGetSymbolAddress(&pmin, g_minbits);
    cudaMemsetAsync(pkv, 0, sizeof(float) * BB * HH * MM * HD, 0);
    cudaMemsetAsync(pks, 0, sizeof(float) * BB * HH * MM, 0);
    cudaMemsetAsync(pmin, 0x7F, 4, 0);   // +huge float init for min

    const int smem2 = (256 * 65 + 32 * 65 + 32 * 68 + 256 * 33 + 32) * 4;
    const int smem3 = (128 * 65 + 32 * 65 + 32 * 68 + 128 * 33 + 32) * 4;
    cudaFuncSetAttribute(k_kv, cudaFuncAttributeMaxDynamicSharedMemorySize, smem2);
    cudaFuncSetAttribute(k_out, cudaFuncAttributeMaxDynamicSharedMemorySize, smem3);

    k_minsq<<<(BB * LL * HH) / 256, 256>>>(k);
    k_kv<<<BB * HH * NSPLIT, 256, smem2>>>(k, v, W);
    k_out<<<BB * HH * (LL / 128), 256, smem3>>>(q, W, out);
}

// round 3
// speedup vs baseline: 1.4989x; 1.4989x over previous
#include <cuda_runtime.h>

#define BB 4
#define LL 4096
#define DD 1024
#define HH 16
#define HD 64
#define MM 256
#define NSPLIT 16
#define LSPL (LL/NSPLIT)   /* 256 */
#define CH 64

#define SCALE 0.17677669529663689f   /* 1024^-0.25 */
#define CF    0.0625f                /* 256^-0.5   */
#define EPSV  1e-4f
#define CEPS  (0.0625f*1e-4f)

typedef unsigned long long ull;

__device__ float    g_kv[BB*HH*MM*HD];   // 4 MB scratch
__device__ float    g_ksum[BB*HH*MM];
__device__ unsigned g_minbits;

// ---- packed f32x2 helpers (Blackwell FFMA2 path: only reachable via PTX) ----
__device__ __forceinline__ ull pk(float lo, float hi) {
    ull r; asm("mov.b64 %0, {%1, %2};" : "=l"(r) : "f"(lo), "f"(hi)); return r;
}
__device__ __forceinline__ float2 upk(ull v) {
    float2 f; asm("mov.b64 {%0, %1}, %2;" : "=f"(f.x), "=f"(f.y) : "l"(v)); return f;
}
__device__ __forceinline__ ull fma2(ull a, ull b, ull c) {
    ull d; asm("fma.rn.f32x2 %0, %1, %2, %3;" : "=l"(d) : "l"(a), "l"(b), "l"(c)); return d;
}
__device__ __forceinline__ ull add2(ull a, ull b) {
    ull d; asm("add.rn.f32x2 %0, %1, %2;" : "=l"(d) : "l"(a), "l"(b)); return d;
}

// FMA-pipe exp: exp(x) = 2^(x*log2e), magic-constant split + degree-6 poly.
__device__ __forceinline__ float fexp(float x) {
    float t = x * 1.4426950408889634f;
    t = fminf(fmaxf(t, -126.0f), 126.0f);
    float z = t + 12582912.0f;                 // 1.5 * 2^23
    int   n = __float_as_int(z) - 0x4B400000;  // round(t)
    float f = t - (float)n;                    // |f| <= 0.5
    float p = 1.54035304e-4f;
    p = fmaf(p, f, 1.33335581e-3f);
    p = fmaf(p, f, 9.61812911e-3f);
    p = fmaf(p, f, 5.55041087e-2f);
    p = fmaf(p, f, 2.40226507e-1f);
    p = fmaf(p, f, 6.93147181e-1f);
    p = fmaf(p, f, 1.0f);
    return __int_as_float((n + 127) << 23) * p;
}

// ---------------- Kernel 1: global min of ||k_scaled||^2 per head-row -------
__global__ void __launch_bounds__(256) k_minsq(const float* __restrict__ Kt) {
    int idx = blockIdx.x * 256 + threadIdx.x;
    const float4* p = (const float4*)Kt + (size_t)idx * 16;
    float s = 0.f;
#pragma unroll
    for (int i = 0; i < 16; i++) {
        float4 v = p[i];
        s = fmaf(v.x, v.x, s); s = fmaf(v.y, v.y, s);
        s = fmaf(v.z, v.z, s); s = fmaf(v.w, v.w, s);
    }
    s *= SCALE * SCALE;
#pragma unroll
    for (int o = 16; o; o >>= 1) s = fminf(s, __shfl_xor_sync(0xffffffffu, s, o));
    if ((threadIdx.x & 31) == 0) atomicMin(&g_minbits, __float_as_uint(s));
}

// ---------------- Kernel 2: k' = phi(k); accumulate kv = k'^T v, ksum -------
// 512 threads. smem: W[kk][m] (260), k[kk][l] (68), v[l][d] (64), kp[l][m] (256)
__global__ void __launch_bounds__(512, 1)
k_kv(const float* __restrict__ Kt, const float* __restrict__ Vt,
     const float* __restrict__ Wt) {
    extern __shared__ float sm[];
    float* W_s  = sm;                 // 64*260
    float* k_s  = W_s + 64 * 260;     // 64*68
    float* v_s  = k_s + 64 * 68;      // 64*64
    float* kp_s = v_s + 64 * 64;      // 64*256

    const int tid = threadIdx.x;
    const int bh  = blockIdx.x >> 4;
    const int spl = blockIdx.x & 15;
    const int b = bh >> 4, hh = bh & 15;
    const float stab = -0.5f * __uint_as_float(g_minbits);

    // Load W transposed: W_s[kk][m] = W[m][kk]
    for (int i = tid; i < 4096; i += 512) {
        int m = i >> 4, kkg = (i & 15) * 4;
        float4 w4 = ((const float4*)Wt)[i];
        W_s[(kkg + 0) * 260 + m] = w4.x;
        W_s[(kkg + 1) * 260 + m] = w4.y;
        W_s[(kkg + 2) * 260 + m] = w4.z;
        W_s[(kkg + 3) * 260 + m] = w4.w;
    }

    // kv tile per thread: 4 m x 8 d (as 4 d-pairs)
    ull acc[4][4];
#pragma unroll
    for (int a = 0; a < 4; a++)
#pragma unroll
        for (int c = 0; c < 4; c++) acc[a][c] = 0ull;
    ull ks2[2] = {0ull, 0ull};

    const int lg = tid >> 5;     // proj: 16 groups x 4 l
    const int mg = tid & 31;     // proj: 32 groups x 8 m
    const int tm = tid >> 3;     // kv:   64 groups x 4 m
    const int td = tid & 7;      // kv:   8 groups x 8 d
    const int l0 = spl * LSPL;
    const float* Kb = Kt + ((size_t)b * LL) * DD + hh * HD;
    const float* Vb = Vt + ((size_t)b * LL) * DD + hh * HD;

    for (int c0 = 0; c0 < LSPL; c0 += CH) {   // 4 chunks
        // load k chunk transposed+scaled, v chunk straight
        for (int i = tid; i < CH * 16; i += 512) {
            int r = i >> 4, c4 = (i & 15) * 4;
            float4 k4 = *(const float4*)(Kb + (size_t)(l0 + c0 + r) * DD + c4);
            k_s[(c4 + 0) * 68 + r] = k4.x * SCALE;
            k_s[(c4 + 1) * 68 + r] = k4.y * SCALE;
            k_s[(c4 + 2) * 68 + r] = k4.z * SCALE;
            k_s[(c4 + 3) * 68 + r] = k4.w * SCALE;
            float4 v4 = *(const float4*)(Vb + (size_t)(l0 + c0 + r) * DD + c4);
            *(float4*)(&v_s[r * 64 + c4]) = v4;
        }
        __syncthreads();

        // proj [64 l, 256 m] + h + phi -> kp_s[l][m]
        {
            ull pacc[4][4];
#pragma unroll
            for (int i = 0; i < 4; i++)
#pragma unroll
                for (int j = 0; j < 4; j++) pacc[i][j] = 0ull;
            ull h2[2] = {0ull, 0ull};
#pragma unroll 8
            for (int kk = 0; kk < 64; kk++) {
                float4 a4 = *(const float4*)&k_s[kk * 68 + lg * 4];
                ull ad0 = pk(a4.x, a4.x), ad1 = pk(a4.y, a4.y);
                ull ad2 = pk(a4.z, a4.z), ad3 = pk(a4.w, a4.w);
                ull ap01 = pk(a4.x, a4.y), ap23 = pk(a4.z, a4.w);
                h2[0] = fma2(ap01, ap01, h2[0]);
                h2[1] = fma2(ap23, ap23, h2[1]);
                float4 wA = *(const float4*)&W_s[kk * 260 + mg * 8];
                float4 wB = *(const float4*)&W_s[kk * 260 + mg * 8 + 4];
                ull w0 = pk(wA.x, wA.y), w1 = pk(wA.z, wA.w);
                ull w2 = pk(wB.x, wB.y), w3 = pk(wB.z, wB.w);
                pacc[0][0] = fma2(ad0, w0, pacc[0][0]);
                pacc[0][1] = fma2(ad0, w1, pacc[0][1]);
                pacc[0][2] = fma2(ad0, w2, pacc[0][2]);
                pacc[0][3] = fma2(ad0, w3, pacc[0][3]);
                pacc[1][0] = fma2(ad1, w0, pacc[1][0]);
                pacc[1][1] = fma2(ad1, w1, pacc[1][1]);
                pacc[1][2] = fma2(ad1, w2, pacc[1][2]);
                pacc[1][3] = fma2(ad1, w3, pacc[1][3]);
                pacc[2][0] = fma2(ad2, w0, pacc[2][0]);
                pacc[2][1] = fma2(ad2, w1, pacc[2][1]);
                pacc[2][2] = fma2(ad2, w2, pacc[2][2]);
                pacc[2][3] = fma2(ad2, w3, pacc[2][3]);
                pacc[3][0] = fma2(ad3, w0, pacc[3][0]);
                pacc[3][1] = fma2(ad3, w1, pacc[3][1]);
                pacc[3][2] = fma2(ad3, w2, pacc[3][2]);
                pacc[3][3] = fma2(ad3, w3, pacc[3][3]);
            }
            float h[4];
            {
                float2 ha = upk(h2[0]), hb = upk(h2[1]);
                h[0] = -0.5f * ha.x; h[1] = -0.5f * ha.y;
                h[2] = -0.5f * hb.x; h[3] = -0.5f * hb.y;
            }
#pragma unroll
            for (int i = 0; i < 4; i++) {
                float hb = h[i] - stab;
                float r0[8];
#pragma unroll
                for (int jp = 0; jp < 4; jp++) {
                    float2 p = upk(pacc[i][jp]);
                    r0[2 * jp]     = fmaf(CF, fexp(hb + p.x), CEPS);
                    r0[2 * jp + 1] = fmaf(CF, fexp(hb + p.y), CEPS);
                }
                float* dst = &kp_s[(lg * 4 + i) * 256 + mg * 8];
                *(float4*)dst       = make_float4(r0[0], r0[1], r0[2], r0[3]);
                *(float4*)(dst + 4) = make_float4(r0[4], r0[5], r0[6], r0[7]);
            }
        }
        __syncthreads();

        // kv[256,64] += kp[64l,256m]^T-slice @ v[64l,64d]
#pragma unroll 8
        for (int ll = 0; ll < CH; ll++) {
            float4 a4 = *(const float4*)&kp_s[ll * 256 + tm * 4];
            ull ad0 = pk(a4.x, a4.x), ad1 = pk(a4.y, a4.y);
            ull ad2 = pk(a4.z, a4.z), ad3 = pk(a4.w, a4.w);
            ks2[0] = add2(ks2[0], pk(a4.x, a4.y));
            ks2[1] = add2(ks2[1], pk(a4.z, a4.w));
            float4 bA = *(const float4*)&v_s[ll * 64 + td * 8];
            float4 bB = *(const float4*)&v_s[ll * 64 + td * 8 + 4];
            ull b0 = pk(bA.x, bA.y), b1 = pk(bA.z, bA.w);
            ull b2 = pk(bB.x, bB.y), b3 = pk(bB.z, bB.w);
            acc[0][0] = fma2(ad0, b0, acc[0][0]);
            acc[0][1] = fma2(ad0, b1, acc[0][1]);
            acc[0][2] = fma2(ad0, b2, acc[0][2]);
            acc[0][3] = fma2(ad0, b3, acc[0][3]);
            acc[1][0] = fma2(ad1, b0, acc[1][0]);
            acc[1][1] = fma2(ad1, b1, acc[1][1]);
            acc[1][2] = fma2(ad1, b2, acc[1][2]);
            acc[1][3] = fma2(ad1, b3, acc[1][3]);
            acc[2][0] = fma2(ad2, b0, acc[2][0]);
            acc[2][1] = fma2(ad2, b1, acc[2][1]);
            acc[2][2] = fma2(ad2, b2, acc[2][2]);
            acc[2][3] = fma2(ad2, b3, acc[2][3]);
            acc[3][0] = fma2(ad3, b0, acc[3][0]);
            acc[3][1] = fma2(ad3, b1, acc[3][1]);
            acc[3][2] = fma2(ad3, b2, acc[3][2]);
            acc[3][3] = fma2(ad3, b3, acc[3][3]);
        }
        __syncthreads();
    }

    float* kvg = g_kv + (size_t)bh * MM * HD;
#pragma unroll
    for (int im = 0; im < 4; im++)
#pragma unroll
        for (int jp = 0; jp < 4; jp++) {
            float2 v2 = upk(acc[im][jp]);
            atomicAdd(&kvg[(tm * 4 + im) * HD + td * 8 + jp * 2],     v2.x);
            atomicAdd(&kvg[(tm * 4 + im) * HD + td * 8 + jp * 2 + 1], v2.y);
        }
    if (td == 0) {
        float2 s0 = upk(ks2[0]), s1 = upk(ks2[1]);
        atomicAdd(&g_ksum[bh * MM + tm * 4 + 0], s0.x);
        atomicAdd(&g_ksum[bh * MM + tm * 4 + 1], s0.y);
        atomicAdd(&g_ksum[bh * MM + tm * 4 + 2], s1.x);
        atomicAdd(&g_ksum[bh * MM + tm * 4 + 3], s1.y);
    }
}

// ---------------- Kernel 3: q' = phi(q); out = (q' @ kv) / (q' . ksum) ------
// 256 threads, 2 CTAs/SM. smem: q[kk][l](132), Wc[kk][m](68), kvc[m][d](64),
// qp[m][l](132), ks[64]
__global__ void __launch_bounds__(256, 2)
k_out(const float* __restrict__ Qt, const float* __restrict__ Wt,
      float* __restrict__ Out) {
    extern __shared__ float sm[];
    float* q_s  = sm;                  // 64*132
    float* Wc   = q_s + 64 * 132;      // 64*68
    float* kvc  = Wc + 64 * 68;        // 64*64
    float* qp   = kvc + 64 * 64;       // 64*132
    float* ks_s = qp + 64 * 132;       // 64

    const int tid = threadIdx.x;
    const int bh  = blockIdx.x >> 5;
    const int lc  = blockIdx.x & 31;
    const int b = bh >> 4, hh = bh & 15;
    const int l0 = lc * 128;
    const float* Qb = Qt + ((size_t)b * LL + l0) * DD + hh * HD;

    // load q transposed + scaled: q_s[kk][l]
    for (int i = tid; i < 128 * 16; i += 256) {
        int r = i >> 4, c4 = (i & 15) * 4;
        float4 q4 = *(const float4*)(Qb + (size_t)r * DD + c4);
        q_s[(c4 + 0) * 132 + r] = q4.x * SCALE;
        q_s[(c4 + 1) * 132 + r] = q4.y * SCALE;
        q_s[(c4 + 2) * 132 + r] = q4.z * SCALE;
        q_s[(c4 + 3) * 132 + r] = q4.w * SCALE;
    }

    ull acc[4][4];
#pragma unroll
    for (int i = 0; i < 4; i++)
#pragma unroll
        for (int j = 0; j < 4; j++) acc[i][j] = 0ull;
    float den[4] = {0, 0, 0, 0};

    const int lg = tid >> 3;    // proj: 32 groups x 4 l (=128)
    const int mg = tid & 7;     // proj: 8 groups x 8 m (=64 chunk)
    const int lgo = lg, td = mg;  // out tile: same split (4 l x 8 d)
    const float* kvg = g_kv + (size_t)bh * MM * HD;
    const float* ksg = g_ksum + bh * MM;

    for (int mc = 0; mc < MM; mc += 64) {   // 4 chunks
        // load W chunk transposed, kv chunk straight, ksum chunk
        for (int i = tid; i < 64 * 16; i += 256) {
            int m = i >> 4, c4 = (i & 15) * 4;
            float4 w4 = ((const float4*)Wt)[(mc + m) * 16 + (i & 15)];
            Wc[(c4 + 0) * 68 + m] = w4.x;
            Wc[(c4 + 1) * 68 + m] = w4.y;
            Wc[(c4 + 2) * 68 + m] = w4.z;
            Wc[(c4 + 3) * 68 + m] = w4.w;
            float4 kv4 = *(const float4*)(kvg + (size_t)(mc + m) * HD + c4);
            *(float4*)&kvc[m * 64 + c4] = kv4;
        }
        if (tid < 64) ks_s[tid] = ksg[mc + tid];
        __syncthreads();

        // proj [128 l, 64 m] + exp -> qp[m][l] (query stab cancels: exp(proj))
        {
            ull pacc[4][4];
#pragma unroll
            for (int i = 0; i < 4; i++)
#pragma unroll
                for (int j = 0; j < 4; j++) pacc[i][j] = 0ull;
#pragma unroll 8
            for (int kk = 0; kk < 64; kk++) {
                float4 a4 = *(const float4*)&q_s[kk * 132 + lg * 4];
                ull ad0 = pk(a4.x, a4.x), ad1 = pk(a4.y, a4.y);
                ull ad2 = pk(a4.z, a4.z), ad3 = pk(a4.w, a4.w);
                float4 wA = *(const float4*)&Wc[kk * 68 + mg * 8];
                float4 wB = *(const float4*)&Wc[kk * 68 + mg * 8 + 4];
                ull w0 = pk(wA.x, wA.y), w1 = pk(wA.z, wA.w);
                ull w2 = pk(wB.x, wB.y), w3 = pk(wB.z, wB.w);
                pacc[0][0] = fma2(ad0, w0, pacc[0][0]);
                pacc[0][1] = fma2(ad0, w1, pacc[0][1]);
                pacc[0][2] = fma2(ad0, w2, pacc[0][2]);
                pacc[0][3] = fma2(ad0, w3, pacc[0][3]);
                pacc[1][0] = fma2(ad1, w0, pacc[1][0]);
                pacc[1][1] = fma2(ad1, w1, pacc[1][1]);
                pacc[1][2] = fma2(ad1, w2, pacc[1][2]);
                pacc[1][3] = fma2(ad1, w3, pacc[1][3]);
                pacc[2][0] = fma2(ad2, w0, pacc[2][0]);
                pacc[2][1] = fma2(ad2, w1, pacc[2][1]);
                pacc[2][2] = fma2(ad2, w2, pacc[2][2]);
                pacc[2][3] = fma2(ad2, w3, pacc[2][3]);
                pacc[3][0] = fma2(ad3, w0, pacc[3][0]);
                pacc[3][1] = fma2(ad3, w1, pacc[3][1]);
                pacc[3][2] = fma2(ad3, w2, pacc[3][2]);
                pacc[3][3] = fma2(ad3, w3, pacc[3][3]);
            }
#pragma unroll
            for (int jp = 0; jp < 4; jp++) {
                float e0[4], e1[4];
#pragma unroll
                for (int i = 0; i < 4; i++) {
                    float2 p = upk(pacc[i][jp]);
                    e0[i] = fmaf(CF, fexp(p.x), CEPS);
                    e1[i] = fmaf(CF, fexp(p.y), CEPS);
                }
                *(float4*)&qp[(mg * 8 + 2 * jp) * 132 + lg * 4] =
                    make_float4(e0[0], e0[1], e0[2], e0[3]);
                *(float4*)&qp[(mg * 8 + 2 * jp + 1) * 132 + lg * 4] =
                    make_float4(e1[0], e1[1], e1[2], e1[3]);
            }
        }
        __syncthreads();

        // out[128,64] += qp^T-slice @ kvc ; den += qp . ks
#pragma unroll 8
        for (int mi = 0; mi < 64; mi++) {
            float4 a4 = *(const float4*)&qp[mi * 132 + lgo * 4];
            ull ad0 = pk(a4.x, a4.x), ad1 = pk(a4.y, a4.y);
            ull ad2 = pk(a4.z, a4.z), ad3 = pk(a4.w, a4.w);
            float ksv = ks_s[mi];
            den[0] = fmaf(a4.x, ksv, den[0]);
            den[1] = fmaf(a4.y, ksv, den[1]);
            den[2] = fmaf(a4.z, ksv, den[2]);
            den[3] = fmaf(a4.w, ksv, den[3]);
            float4 bA = *(const float4*)&kvc[mi * 64 + td * 8];
            float4 bB = *(const float4*)&kvc[mi * 64 + td * 8 + 4];
            ull b0 = pk(bA.x, bA.y), b1 = pk(bA.z, bA.w);
            ull b2 = pk(bB.x, bB.y), b3 = pk(bB.z, bB.w);
            acc[0][0] = fma2(ad0, b0, acc[0][0]);
            acc[0][1] = fma2(ad0, b1, acc[0][1]);
            acc[0][2] = fma2(ad0, b2, acc[0][2]);
            acc[0][3] = fma2(ad0, b3, acc[0][3]);
            acc[1][0] = fma2(ad1, b0, acc[1][0]);
            acc[1][1] = fma2(ad1, b1, acc[1][1]);
            acc[1][2] = fma2(ad1, b2, acc[1][2]);
            acc[1][3] = fma2(ad1, b3, acc[1][3]);
            acc[2][0] = fma2(ad2, b0, acc[2][0]);
            acc[2][1] = fma2(ad2, b1, acc[2][1]);
            acc[2][2] = fma2(ad2, b2, acc[2][2]);
            acc[2][3] = fma2(ad2, b3, acc[2][3]);
            acc[3][0] = fma2(ad3, b0, acc[3][0]);
            acc[3][1] = fma2(ad3, b1, acc[3][1]);
            acc[3][2] = fma2(ad3, b2, acc[3][2]);
            acc[3][3] = fma2(ad3, b3, acc[3][3]);
        }
        __syncthreads();
    }

    float* Ob = Out + ((size_t)b * LL + l0) * DD + hh * HD;
#pragma unroll
    for (int i = 0; i < 4; i++) {
        float dd = den[i];
        if (fabsf(dd) <= EPSV) dd += 2.f * EPSV;
        float inv = 1.0f / dd;
        float2 o0 = upk(acc[i][0]), o1 = upk(acc[i][1]);
        float2 o2 = upk(acc[i][2]), o3 = upk(acc[i][3]);
        int l = lgo * 4 + i;
        float4 r0 = make_float4(o0.x * inv, o0.y * inv, o1.x * inv, o1.y * inv);
        float4 r1 = make_float4(o2.x * inv, o2.y * inv, o3.x * inv, o3.y * inv);
        *(float4*)(Ob + (size_t)l * DD + td * 8)     = r0;
        *(float4*)(Ob + (size_t)l * DD + td * 8 + 4) = r1;
    }
}

extern "C" void kernel_launch(void* const* d_in, const int* in_sizes, int n_in,
                              void* d_out, int out_size) {
    const float* q = (const float*)d_in[0];
    const float* k = (const float*)d_in[1];
    const float* v = (const float*)d_in[2];
    const float* W = (const float*)d_in[3];
    float* out = (float*)d_out;

    void *pkv, *pks, *pmin;
    cudaGetSymbolAddress(&pkv, g_kv);
    cudaGetSymbolAddress(&pks, g_ksum);
    cudaGetSymbolAddress(&pmin, g_minbits);
    cudaMemsetAsync(pkv, 0, sizeof(float) * BB * HH * MM * HD, 0);
    cudaMemsetAsync(pks, 0, sizeof(float) * BB * HH * MM, 0);
    cudaMemsetAsync(pmin, 0x7F, 4, 0);   // +huge float init for min

    const int smemKV  = (64 * 260 + 64 * 68 + 64 * 64 + 64 * 256) * 4;
    const int smemOUT = (64 * 132 + 64 * 68 + 64 * 64 + 64 * 132 + 64) * 4;
    cudaFuncSetAttribute(k_kv, cudaFuncAttributeMaxDynamicSharedMemorySize, smemKV);
    cudaFuncSetAttribute(k_out, cudaFuncAttributeMaxDynamicSharedMemorySize, smemOUT);

    k_minsq<<<(BB * LL * HH) / 256, 256>>>(k);
    k_kv<<<BB * HH * NSPLIT, 512, smemKV>>>(k, v, W);
    k_out<<<BB * HH * (LL / 128), 256, smemOUT>>>(q, W, out);
}

// round 4
// speedup vs baseline: 1.4990x; 1.0000x over previous
#include <cuda_runtime.h>

#define BB 4
#define LL 4096
#define DD 1024
#define HH 16
#define HD 64
#define MM 256
#define NSPLIT 16
#define LSPL (LL/NSPLIT)   /* 256 */
#define CH 64

#define SCALE 0.17677669529663689f   /* 1024^-0.25 */
#define CF    0.0625f                /* 256^-0.5   */
#define EPSV  1e-4f
#define CEPS  (0.0625f*1e-4f)

typedef unsigned long long ull;

__device__ float    g_kv[BB*HH*MM*HD];   // 4 MB scratch
__device__ float    g_ksum[BB*HH*MM];
__device__ unsigned g_minbits;

// ---- packed f32x2 helpers (Blackwell FFMA2 path: only reachable via PTX) ----
__device__ __forceinline__ ull pk(float lo, float hi) {
    ull r; asm("mov.b64 %0, {%1, %2};" : "=l"(r) : "f"(lo), "f"(hi)); return r;
}
__device__ __forceinline__ float2 upk(ull v) {
    float2 f; asm("mov.b64 {%0, %1}, %2;" : "=f"(f.x), "=f"(f.y) : "l"(v)); return f;
}
__device__ __forceinline__ ull fma2(ull a, ull b, ull c) {
    ull d; asm("fma.rn.f32x2 %0, %1, %2, %3;" : "=l"(d) : "l"(a), "l"(b), "l"(c)); return d;
}
__device__ __forceinline__ ull add2(ull a, ull b) {
    ull d; asm("add.rn.f32x2 %0, %1, %2;" : "=l"(d) : "l"(a), "l"(b)); return d;
}

// FMA-pipe exp: exp(x) = 2^(x*log2e), magic-constant split + degree-6 poly.
__device__ __forceinline__ float fexp(float x) {
    float t = x * 1.4426950408889634f;
    t = fminf(fmaxf(t, -126.0f), 126.0f);
    float z = t + 12582912.0f;                 // 1.5 * 2^23
    int   n = __float_as_int(z) - 0x4B400000;  // round(t)
    float f = t - (float)n;                    // |f| <= 0.5
    float p = 1.54035304e-4f;
    p = fmaf(p, f, 1.33335581e-3f);
    p = fmaf(p, f, 9.61812911e-3f);
    p = fmaf(p, f, 5.55041087e-2f);
    p = fmaf(p, f, 2.40226507e-1f);
    p = fmaf(p, f, 6.93147181e-1f);
    p = fmaf(p, f, 1.0f);
    return __int_as_float((n + 127) << 23) * p;
}

// ---------------- Kernel 1: global min of ||k_scaled||^2 per head-row -------
__global__ void __launch_bounds__(256) k_minsq(const float* __restrict__ Kt) {
    int idx = blockIdx.x * 256 + threadIdx.x;
    const float4* p = (const float4*)Kt + (size_t)idx * 16;
    float s = 0.f;
#pragma unroll
    for (int i = 0; i < 16; i++) {
        float4 v = p[i];
        s = fmaf(v.x, v.x, s); s = fmaf(v.y, v.y, s);
        s = fmaf(v.z, v.z, s); s = fmaf(v.w, v.w, s);
    }
    s *= SCALE * SCALE;
#pragma unroll
    for (int o = 16; o; o >>= 1) s = fminf(s, __shfl_xor_sync(0xffffffffu, s, o));
    if ((threadIdx.x & 31) == 0) atomicMin(&g_minbits, __float_as_uint(s));
}

// ---------------- Kernel 2: k' = phi(k); accumulate kv = k'^T v, ksum -------
// 512 threads. smem: W[kk][m] (260), k[kk][l] (68), v[l][d] (64), kp[l][m] (256)
__global__ void __launch_bounds__(512, 1)
k_kv(const float* __restrict__ Kt, const float* __restrict__ Vt,
     const float* __restrict__ Wt) {
    extern __shared__ float sm[];
    float* W_s  = sm;                 // 64*260
    float* k_s  = W_s + 64 * 260;     // 64*68
    float* v_s  = k_s + 64 * 68;      // 64*64
    float* kp_s = v_s + 64 * 64;      // 64*256

    const int tid = threadIdx.x;
    const int bh  = blockIdx.x >> 4;
    const int spl = blockIdx.x & 15;
    const int b = bh >> 4, hh = bh & 15;
    const float stab = -0.5f * __uint_as_float(g_minbits);

    // Load W transposed: W_s[kk][m] = W[m][kk]
    for (int i = tid; i < 4096; i += 512) {
        int m = i >> 4, kkg = (i & 15) * 4;
        float4 w4 = ((const float4*)Wt)[i];
        W_s[(kkg + 0) * 260 + m] = w4.x;
        W_s[(kkg + 1) * 260 + m] = w4.y;
        W_s[(kkg + 2) * 260 + m] = w4.z;
        W_s[(kkg + 3) * 260 + m] = w4.w;
    }

    // kv tile per thread: 4 m x 8 d (as 4 d-pairs)
    ull acc[4][4];
#pragma unroll
    for (int a = 0; a < 4; a++)
#pragma unroll
        for (int c = 0; c < 4; c++) acc[a][c] = 0ull;
    ull ks2[2] = {0ull, 0ull};

    const int lg = tid >> 5;     // proj: 16 groups x 4 l
    const int mg = tid & 31;     // proj: 32 groups x 8 m
    const int tm = tid >> 3;     // kv:   64 groups x 4 m
    const int td = tid & 7;      // kv:   8 groups x 8 d
    const int l0 = spl * LSPL;
    const float* Kb = Kt + ((size_t)b * LL) * DD + hh * HD;
    const float* Vb = Vt + ((size_t)b * LL) * DD + hh * HD;

    for (int c0 = 0; c0 < LSPL; c0 += CH) {   // 4 chunks
        // load k chunk transposed+scaled, v chunk straight
        for (int i = tid; i < CH * 16; i += 512) {
            int r = i >> 4, c4 = (i & 15) * 4;
            float4 k4 = *(const float4*)(Kb + (size_t)(l0 + c0 + r) * DD + c4);
            k_s[(c4 + 0) * 68 + r] = k4.x * SCALE;
            k_s[(c4 + 1) * 68 + r] = k4.y * SCALE;
            k_s[(c4 + 2) * 68 + r] = k4.z * SCALE;
            k_s[(c4 + 3) * 68 + r] = k4.w * SCALE;
            float4 v4 = *(const float4*)(Vb + (size_t)(l0 + c0 + r) * DD + c4);
            *(float4*)(&v_s[r * 64 + c4]) = v4;
        }
        __syncthreads();

        // proj [64 l, 256 m] + h + phi -> kp_s[l][m]
        {
            ull pacc[4][4];
#pragma unroll
            for (int i = 0; i < 4; i++)
#pragma unroll
                for (int j = 0; j < 4; j++) pacc[i][j] = 0ull;
            ull h2[2] = {0ull, 0ull};
#pragma unroll 8
            for (int kk = 0; kk < 64; kk++) {
                float4 a4 = *(const float4*)&k_s[kk * 68 + lg * 4];
                ull ad0 = pk(a4.x, a4.x), ad1 = pk(a4.y, a4.y);
                ull ad2 = pk(a4.z, a4.z), ad3 = pk(a4.w, a4.w);
                ull ap01 = pk(a4.x, a4.y), ap23 = pk(a4.z, a4.w);
                h2[0] = fma2(ap01, ap01, h2[0]);
                h2[1] = fma2(ap23, ap23, h2[1]);
                float4 wA = *(const float4*)&W_s[kk * 260 + mg * 8];
                float4 wB = *(const float4*)&W_s[kk * 260 + mg * 8 + 4];
                ull w0 = pk(wA.x, wA.y), w1 = pk(wA.z, wA.w);
                ull w2 = pk(wB.x, wB.y), w3 = pk(wB.z, wB.w);
                pacc[0][0] = fma2(ad0, w0, pacc[0][0]);
                pacc[0][1] = fma2(ad0, w1, pacc[0][1]);
                pacc[0][2] = fma2(ad0, w2, pacc[0][2]);
                pacc[0][3] = fma2(ad0, w3, pacc[0][3]);
                pacc[1][0] = fma2(ad1, w0, pacc[1][0]);
                pacc[1][1] = fma2(ad1, w1, pacc[1][1]);
                pacc[1][2] = fma2(ad1, w2, pacc[1][2]);
                pacc[1][3] = fma2(ad1, w3, pacc[1][3]);
                pacc[2][0] = fma2(ad2, w0, pacc[2][0]);
                pacc[2][1] = fma2(ad2, w1, pacc[2][1]);
                pacc[2][2] = fma2(ad2, w2, pacc[2][2]);
                pacc[2][3] = fma2(ad2, w3, pacc[2][3]);
                pacc[3][0] = fma2(ad3, w0, pacc[3][0]);
                pacc[3][1] = fma2(ad3, w1, pacc[3][1]);
                pacc[3][2] = fma2(ad3, w2, pacc[3][2]);
                pacc[3][3] = fma2(ad3, w3, pacc[3][3]);
            }
            float h[4];
            {
                float2 ha = upk(h2[0]), hb = upk(h2[1]);
                h[0] = -0.5f * ha.x; h[1] = -0.5f * ha.y;
                h[2] = -0.5f * hb.x; h[3] = -0.5f * hb.y;
            }
#pragma unroll
            for (int i = 0; i < 4; i++) {
                float hb = h[i] - stab;
                float r0[8];
#pragma unroll
                for (int jp = 0; jp < 4; jp++) {
                    float2 p = upk(pacc[i][jp]);
                    r0[2 * jp]     = fmaf(CF, fexp(hb + p.x), CEPS);
                    r0[2 * jp + 1] = fmaf(CF, fexp(hb + p.y), CEPS);
                }
                float* dst = &kp_s[(lg * 4 + i) * 256 + mg * 8];
                *(float4*)dst       = make_float4(r0[0], r0[1], r0[2], r0[3]);
                *(float4*)(dst + 4) = make_float4(r0[4], r0[5], r0[6], r0[7]);
            }
        }
        __syncthreads();

        // kv[256,64] += kp[64l,256m]^T-slice @ v[64l,64d]
#pragma unroll 8
        for (int ll = 0; ll < CH; ll++) {
            float4 a4 = *(const float4*)&kp_s[ll * 256 + tm * 4];
            ull ad0 = pk(a4.x, a4.x), ad1 = pk(a4.y, a4.y);
            ull ad2 = pk(a4.z, a4.z), ad3 = pk(a4.w, a4.w);
            ks2[0] = add2(ks2[0], pk(a4.x, a4.y));
            ks2[1] = add2(ks2[1], pk(a4.z, a4.w));
            float4 bA = *(const float4*)&v_s[ll * 64 + td * 8];
            float4 bB = *(const float4*)&v_s[ll * 64 + td * 8 + 4];
            ull b0 = pk(bA.x, bA.y), b1 = pk(bA.z, bA.w);
            ull b2 = pk(bB.x, bB.y), b3 = pk(bB.z, bB.w);
            acc[0][0] = fma2(ad0, b0, acc[0][0]);
            acc[0][1] = fma2(ad0, b1, acc[0][1]);
            acc[0][2] = fma2(ad0, b2, acc[0][2]);
            acc[0][3] = fma2(ad0, b3, acc[0][3]);
            acc[1][0] = fma2(ad1, b0, acc[1][0]);
            acc[1][1] = fma2(ad1, b1, acc[1][1]);
            acc[1][2] = fma2(ad1, b2, acc[1][2]);
            acc[1][3] = fma2(ad1, b3, acc[1][3]);
            acc[2][0] = fma2(ad2, b0, acc[2][0]);
            acc[2][1] = fma2(ad2, b1, acc[2][1]);
            acc[2][2] = fma2(ad2, b2, acc[2][2]);
            acc[2][3] = fma2(ad2, b3, acc[2][3]);
            acc[3][0] = fma2(ad3, b0, acc[3][0]);
            acc[3][1] = fma2(ad3, b1, acc[3][1]);
            acc[3][2] = fma2(ad3, b2, acc[3][2]);
            acc[3][3] = fma2(ad3, b3, acc[3][3]);
        }
        __syncthreads();
    }

    float* kvg = g_kv + (size_t)bh * MM * HD;
#pragma unroll
    for (int im = 0; im < 4; im++)
#pragma unroll
        for (int jp = 0; jp < 4; jp++) {
            float2 v2 = upk(acc[im][jp]);
            atomicAdd(&kvg[(tm * 4 + im) * HD + td * 8 + jp * 2],     v2.x);
            atomicAdd(&kvg[(tm * 4 + im) * HD + td * 8 + jp * 2 + 1], v2.y);
        }
    if (td == 0) {
        float2 s0 = upk(ks2[0]), s1 = upk(ks2[1]);
        atomicAdd(&g_ksum[bh * MM + tm * 4 + 0], s0.x);
        atomicAdd(&g_ksum[bh * MM + tm * 4 + 1], s0.y);
        atomicAdd(&g_ksum[bh * MM + tm * 4 + 2], s1.x);
        atomicAdd(&g_ksum[bh * MM + tm * 4 + 3], s1.y);
    }
}

// ---------------- Kernel 3: q' = phi(q); out = (q' @ kv) / (q' . ksum) ------
// 256 threads, 2 CTAs/SM. smem: q[kk][l](132), Wc[kk][m](68), kvc[m][d](64),
// qp[m][l](132), ks[64]
__global__ void __launch_bounds__(256, 2)
k_out(const float* __restrict__ Qt, const float* __restrict__ Wt,
      float* __restrict__ Out) {
    extern __shared__ float sm[];
    float* q_s  = sm;                  // 64*132
    float* Wc   = q_s + 64 * 132;      // 64*68
    float* kvc  = Wc + 64 * 68;        // 64*64
    float* qp   = kvc + 64 * 64;       // 64*132
    float* ks_s = qp + 64 * 132;       // 64

    const int tid = threadIdx.x;
    const int bh  = blockIdx.x >> 5;
    const int lc  = blockIdx.x & 31;
    const int b = bh >> 4, hh = bh & 15;
    const int l0 = lc * 128;
    const float* Qb = Qt + ((size_t)b * LL + l0) * DD + hh * HD;

    // load q transposed + scaled: q_s[kk][l]
    for (int i = tid; i < 128 * 16; i += 256) {
        int r = i >> 4, c4 = (i & 15) * 4;
        float4 q4 = *(const float4*)(Qb + (size_t)r * DD + c4);
        q_s[(c4 + 0) * 132 + r] = q4.x * SCALE;
        q_s[(c4 + 1) * 132 + r] = q4.y * SCALE;
        q_s[(c4 + 2) * 132 + r] = q4.z * SCALE;
        q_s[(c4 + 3) * 132 + r] = q4.w * SCALE;
    }

    ull acc[4][4];
#pragma unroll
    for (int i = 0; i < 4; i++)
#pragma unroll
        for (int j = 0; j < 4; j++) acc[i][j] = 0ull;
    float den[4] = {0, 0, 0, 0};

    const int lg = tid >> 3;    // proj: 32 groups x 4 l (=128)
    const int mg = tid & 7;     // proj: 8 groups x 8 m (=64 chunk)
    const int lgo = lg, td = mg;  // out tile: same split (4 l x 8 d)
    const float* kvg = g_kv + (size_t)bh * MM * HD;
    const float* ksg = g_ksum + bh * MM;

    for (int mc = 0; mc < MM; mc += 64) {   // 4 chunks
        // load W chunk transposed, kv chunk straight, ksum chunk
        for (int i = tid; i < 64 * 16; i += 256) {
            int m = i >> 4, c4 = (i & 15) * 4;
            float4 w4 = ((const float4*)Wt)[(mc + m) * 16 + (i & 15)];
            Wc[(c4 + 0) * 68 + m] = w4.x;
            Wc[(c4 + 1) * 68 + m] = w4.y;
            Wc[(c4 + 2) * 68 + m] = w4.z;
            Wc[(c4 + 3) * 68 + m] = w4.w;
            float4 kv4 = *(const float4*)(kvg + (size_t)(mc + m) * HD + c4);
            *(float4*)&kvc[m * 64 + c4] = kv4;
        }
        if (tid < 64) ks_s[tid] = ksg[mc + tid];
        __syncthreads();

        // proj [128 l, 64 m] + exp -> qp[m][l] (query stab cancels: exp(proj))
        {
            ull pacc[4][4];
#pragma unroll
            for (int i = 0; i < 4; i++)
#pragma unroll
                for (int j = 0; j < 4; j++) pacc[i][j] = 0ull;
#pragma unroll 8
            for (int kk = 0; kk < 64; kk++) {
                float4 a4 = *(const float4*)&q_s[kk * 132 + lg * 4];
                ull ad0 = pk(a4.x, a4.x), ad1 = pk(a4.y, a4.y);
                ull ad2 = pk(a4.z, a4.z), ad3 = pk(a4.w, a4.w);
                float4 wA = *(const float4*)&Wc[kk * 68 + mg * 8];
                float4 wB = *(const float4*)&Wc[kk * 68 + mg * 8 + 4];
                ull w0 = pk(wA.x, wA.y), w1 = pk(wA.z, wA.w);
                ull w2 = pk(wB.x, wB.y), w3 = pk(wB.z, wB.w);
                pacc[0][0] = fma2(ad0, w0, pacc[0][0]);
                pacc[0][1] = fma2(ad0, w1, pacc[0][1]);
                pacc[0][2] = fma2(ad0, w2, pacc[0][2]);
                pacc[0][3] = fma2(ad0, w3, pacc[0][3]);
                pacc[1][0] = fma2(ad1, w0, pacc[1][0]);
                pacc[1][1] = fma2(ad1, w1, pacc[1][1]);
                pacc[1][2] = fma2(ad1, w2, pacc[1][2]);
                pacc[1][3] = fma2(ad1, w3, pacc[1][3]);
                pacc[2][0] = fma2(ad2, w0, pacc[2][0]);
                pacc[2][1] = fma2(ad2, w1, pacc[2][1]);
                pacc[2][2] = fma2(ad2, w2, pacc[2][2]);
                pacc[2][3] = fma2(ad2, w3, pacc[2][3]);
                pacc[3][0] = fma2(ad3, w0, pacc[3][0]);
                pacc[3][1] = fma2(ad3, w1, pacc[3][1]);
                pacc[3][2] = fma2(ad3, w2, pacc[3][2]);
                pacc[3][3] = fma2(ad3, w3, pacc[3][3]);
            }
#pragma unroll
            for (int jp = 0; jp < 4; jp++) {
                float e0[4], e1[4];
#pragma unroll
                for (int i = 0; i < 4; i++) {
                    float2 p = upk(pacc[i][jp]);
                    e0[i] = fmaf(CF, fexp(p.x), CEPS);
                    e1[i] = fmaf(CF, fexp(p.y), CEPS);
                }
                *(float4*)&qp[(mg * 8 + 2 * jp) * 132 + lg * 4] =
                    make_float4(e0[0], e0[1], e0[2], e0[3]);
                *(float4*)&qp[(mg * 8 + 2 * jp + 1) * 132 + lg * 4] =
                    make_float4(e1[0], e1[1], e1[2], e1[3]);
            }
        }
        __syncthreads();

        // out[128,64] += qp^T-slice @ kvc ; den += qp . ks
#pragma unroll 8
        for (int mi = 0; mi < 64; mi++) {
            float4 a4 = *(const float4*)&qp[mi * 132 + lgo * 4];
            ull ad0 = pk(a4.x, a4.x), ad1 = pk(a4.y, a4.y);
            ull ad2 = pk(a4.z, a4.z), ad3 = pk(a4.w, a4.w);
            float ksv = ks_s[mi];
            den[0] = fmaf(a4.x, ksv, den[0]);
            den[1] = fmaf(a4.y, ksv, den[1]);
            den[2] = fmaf(a4.z, ksv, den[2]);
            den[3] = fmaf(a4.w, ksv, den[3]);
            float4 bA = *(const float4*)&kvc[mi * 64 + td * 8];
            float4 bB = *(const float4*)&kvc[mi * 64 + td * 8 + 4];
            ull b0 = pk(bA.x, bA.y), b1 = pk(bA.z, bA.w);
            ull b2 = pk(bB.x, bB.y), b3 = pk(bB.z, bB.w);
            acc[0][0] = fma2(ad0, b0, acc[0][0]);
            acc[0][1] = fma2(ad0, b1, acc[0][1]);
            acc[0][2] = fma2(ad0, b2, acc[0][2]);
            acc[0][3] = fma2(ad0, b3, acc[0][3]);
            acc[1][0] = fma2(ad1, b0, acc[1][0]);
            acc[1][1] = fma2(ad1, b1, acc[1][1]);
            acc[1][2] = fma2(ad1, b2, acc[1][2]);
            acc[1][3] = fma2(ad1, b3, acc[1][3]);
            acc[2][0] = fma2(ad2, b0, acc[2][0]);
            acc[2][1] = fma2(ad2, b1, acc[2][1]);
            acc[2][2] = fma2(ad2, b2, acc[2][2]);
            acc[2][3] = fma2(ad2, b3, acc[2][3]);
            acc[3][0] = fma2(ad3, b0, acc[3][0]);
            acc[3][1] = fma2(ad3, b1, acc[3][1]);
            acc[3][2] = fma2(ad3, b2, acc[3][2]);
            acc[3][3] = fma2(ad3, b3, acc[3][3]);
        }
        __syncthreads();
    }

    float* Ob = Out + ((size_t)b * LL + l0) * DD + hh * HD;
#pragma unroll
    for (int i = 0; i < 4; i++) {
        float dd = den[i];
        if (fabsf(dd) <= EPSV) dd += 2.f * EPSV;
        float inv = 1.0f / dd;
        float2 o0 = upk(acc[i][0]), o1 = upk(acc[i][1]);
        float2 o2 = upk(acc[i][2]), o3 = upk(acc[i][3]);
        int l = lgo * 4 + i;
        float4 r0 = make_float4(o0.x * inv, o0.y * inv, o1.x * inv, o1.y * inv);
        float4 r1 = make_float4(o2.x * inv, o2.y * inv, o3.x * inv, o3.y * inv);
        *(float4*)(Ob + (size_t)l * DD + td * 8)     = r0;
        *(float4*)(Ob + (size_t)l * DD + td * 8 + 4) = r1;
    }
}

extern "C" void kernel_launch(void* const* d_in, const int* in_sizes, int n_in,
                              void* d_out, int out_size) {
    const float* q = (const float*)d_in[0];
    const float* k = (const float*)d_in[1];
    const float* v = (const float*)d_in[2];
    const float* W = (const float*)d_in[3];
    float* out = (float*)d_out;

    void *pkv, *pks, *pmin;
    cudaGetSymbolAddress(&pkv, g_kv);
    cudaGetSymbolAddress(&pks, g_ksum);
    cudaGetSymbolAddress(&pmin, g_minbits);
    cudaMemsetAsync(pkv, 0, sizeof(float) * BB * HH * MM * HD, 0);
    cudaMemsetAsync(pks, 0, sizeof(float) * BB * HH * MM, 0);
    cudaMemsetAsync(pmin, 0x7F, 4, 0);   // +huge float init for min

    const int smemKV  = (64 * 260 + 64 * 68 + 64 * 64 + 64 * 256) * 4;
    const int smemOUT = (64 * 132 + 64 * 68 + 64 * 64 + 64 * 132 + 64) * 4;
    cudaFuncSetAttribute(k_kv, cudaFuncAttributeMaxDynamicSharedMemorySize, smemKV);
    cudaFuncSetAttribute(k_out, cudaFuncAttributeMaxDynamicSharedMemorySize, smemOUT);

    k_minsq<<<(BB * LL * HH) / 256, 256>>>(k);
    k_kv<<<BB * HH * NSPLIT, 512, smemKV>>>(k, v, W);
    k_out<<<BB * HH * (LL / 128), 256, smemOUT>>>(q, W, out);
}

// round 6
// speedup vs baseline: 3.4213x; 2.2824x over previous
#include <cuda_runtime.h>
#include <cuda_bf16.h>
#include <cstdint>

#define BB 4
#define LL 4096
#define DD 1024
#define HH 16
#define MM 256

#define SCALE 0.17677669529663689f   /* 1024^-0.25 */
#define CF    0.0625f                /* 256^-0.5   */
#define EPSV  1e-4f
#define CEPS  (0.0625f*1e-4f)

__device__ float    g_kv[BB*HH*72*256];   /* [bh][d(0..63)|ksum(64)|pad][m] */
__device__ unsigned g_minbits;

/* ---- k_kv smem map (bytes). strides: 144 (72el), 528 (264el) ---- */
#define SB_H    0          /* 128 floats */
#define SB_WHI  512        /* [256 m][64 k] stride 144 -> 36864 */
#define SB_WLO  37376
#define SB_KHI  74240      /* [128 l][64 k] stride 144 -> 18432 */
#define SB_KLO  92672
#define SB_KPH  111104     /* k' [64 l][256 m] stride 528 -> 33792 */
#define SB_KPL  144896
#define SB_VHI  178688     /* v [128 l][72 d] stride 144 -> 18432 */
#define SB_VLO  197120
#define SB_SMEM 215552

/* ---- k_out smem map ---- */
#define SC_WHI  0          /* 36864 */
#define SC_WLO  36864
#define SC_QHI  73728      /* [128 l][64 k] stride 144 -> 18432 */
#define SC_QLO  92160
#define SC_QPH  110592     /* q' [128 l][128 m] stride 272 -> 34816 */
#define SC_QPL  145408
#define SC_KVH  180224     /* kv [72 d][128 m] stride 272 -> 19584 */
#define SC_KVL  199808
#define SC_SMEM 219392

/* ------------------------------- helpers -------------------------------- */
__device__ __forceinline__ uint32_t smem_u32(const void* p) {
    uint32_t a;
    asm("{ .reg .u64 t; cvta.to.shared.u64 t, %1; cvt.u32.u64 %0, t; }" : "=r"(a) : "l"(p));
    return a;
}
__device__ __forceinline__ void ldsm4(uint32_t* r, uint32_t a) {
    asm volatile("ldmatrix.sync.aligned.m8n8.x4.shared.b16 {%0,%1,%2,%3}, [%4];"
                 : "=r"(r[0]), "=r"(r[1]), "=r"(r[2]), "=r"(r[3]) : "r"(a));
}
__device__ __forceinline__ void ldsm4t(uint32_t* r, uint32_t a) {
    asm volatile("ldmatrix.sync.aligned.m8n8.x4.trans.shared.b16 {%0,%1,%2,%3}, [%4];"
                 : "=r"(r[0]), "=r"(r[1]), "=r"(r[2]), "=r"(r[3]) : "r"(a));
}
__device__ __forceinline__ void ldsm2(uint32_t* r, uint32_t a) {
    asm volatile("ldmatrix.sync.aligned.m8n8.x2.shared.b16 {%0,%1}, [%2];"
                 : "=r"(r[0]), "=r"(r[1]) : "r"(a));
}
__device__ __forceinline__ void ldsm2t(uint32_t* r, uint32_t a) {
    asm volatile("ldmatrix.sync.aligned.m8n8.x2.trans.shared.b16 {%0,%1}, [%2];"
                 : "=r"(r[0]), "=r"(r[1]) : "r"(a));
}
__device__ __forceinline__ void mmabf(float* d, const uint32_t* a, const uint32_t* b) {
    asm volatile("mma.sync.aligned.m16n8k16.row.col.f32.bf16.bf16.f32 "
                 "{%0,%1,%2,%3},{%4,%5,%6,%7},{%8,%9},{%0,%1,%2,%3};"
                 : "+f"(d[0]), "+f"(d[1]), "+f"(d[2]), "+f"(d[3])
                 : "r"(a[0]), "r"(a[1]), "r"(a[2]), "r"(a[3]), "r"(b[0]), "r"(b[1]));
}
__device__ __forceinline__ float fexp(float x) {
    float t = x * 1.4426950408889634f;
    t = fminf(fmaxf(t, -126.0f), 126.0f);
    float z = t + 12582912.0f;
    int   n = __float_as_int(z) - 0x4B400000;
    float f = t - (float)n;
    float p = 1.54035304e-4f;
    p = fmaf(p, f, 1.33335581e-3f);
    p = fmaf(p, f, 9.61812911e-3f);
    p = fmaf(p, f, 5.55041087e-2f);
    p = fmaf(p, f, 2.40226507e-1f);
    p = fmaf(p, f, 6.93147181e-1f);
    p = fmaf(p, f, 1.0f);
    return __int_as_float((n + 127) << 23) * p;
}
__device__ __forceinline__ float bhi_f(float x) {
    return __bfloat162float(__float2bfloat16_rn(x));
}
__device__ __forceinline__ uint32_t pk2(float a, float b) {
    __nv_bfloat162 h = __floats2bfloat162_rn(a, b);
    return *(uint32_t*)&h;
}
/* split float4 -> 4 hi-bf16 (8B) + 4 lo-bf16 (8B) */
__device__ __forceinline__ void split4u(char* hi, char* lo, float4 w) {
    float hx = bhi_f(w.x), hy = bhi_f(w.y), hz = bhi_f(w.z), hw = bhi_f(w.w);
    *(uint2*)hi = make_uint2(pk2(hx, hy), pk2(hz, hw));
    *(uint2*)lo = make_uint2(pk2(w.x - hx, w.y - hy), pk2(w.z - hz, w.w - hw));
}

/* ---------------- Kernel 1: global min ||k_scaled||^2 -------------------- */
__global__ void __launch_bounds__(256) k_minsq(const float* __restrict__ Kt) {
    int idx = blockIdx.x * 256 + threadIdx.x;
    const float4* p = (const float4*)Kt + (size_t)idx * 16;
    float s = 0.f;
#pragma unroll
    for (int i = 0; i < 16; i++) {
        float4 v = p[i];
        s = fmaf(v.x, v.x, s); s = fmaf(v.y, v.y, s);
        s = fmaf(v.z, v.z, s); s = fmaf(v.w, v.w, s);
    }
    s *= SCALE * SCALE;
#pragma unroll
    for (int o = 16; o; o >>= 1) s = fminf(s, __shfl_xor_sync(0xffffffffu, s, o));
    if ((threadIdx.x & 31) == 0) atomicMin(&g_minbits, __float_as_uint(s));
}

/* ---------------- Kernel B: k'=phi(k); kv += k'^T [v|1] ------------------ */
__global__ void __launch_bounds__(256, 1)
k_kv(const float* __restrict__ Kt, const float* __restrict__ Vt,
     const float* __restrict__ Wt) {
    extern __shared__ char sm[];
    const uint32_t s = smem_u32(sm);
    float* h_s = (float*)sm;
    const int tid = threadIdx.x, lane = tid & 31, w = tid >> 5;
    const int bh = blockIdx.x >> 3, spl = blockIdx.x & 7;
    const int b = bh >> 4, hh = bh & 15;
    const int l0 = spl * 512;
    const float stab = -0.5f * __uint_as_float(g_minbits);
    const int q = lane & 3, r = lane >> 2;

    /* stage W hi/lo [m][k] */
    for (int i = tid; i < 4096; i += 256) {
        int m = i >> 4, cb = (i & 15) * 8;
        split4u(sm + SB_WHI + m * 144 + cb, sm + SB_WLO + m * 144 + cb,
                ((const float4*)Wt)[i]);
    }
    /* v cols 64..71: ones + pad (constant across chunks) */
    for (int i = tid; i < 1024; i += 256) {
        int l = i >> 3, cc = 64 + (i & 7);
        *(uint16_t*)(sm + SB_VHI + l * 144 + cc * 2) = (cc == 64) ? 0x3F80 : 0;
        *(uint16_t*)(sm + SB_VLO + l * 144 + cc * 2) = 0;
    }

    float D2[2][9][4];
#pragma unroll
    for (int a = 0; a < 2; a++)
#pragma unroll
        for (int j = 0; j < 9; j++)
#pragma unroll
            for (int e = 0; e < 4; e++) D2[a][j][e] = 0.f;

    for (int c = 0; c < 4; c++) {
        /* ---- stage k (hi/lo + h) and v (hi/lo), 128 rows each ---- */
        if (tid < 128) {
            int l = tid;
            const float4* kp = (const float4*)(Kt + ((size_t)(b * LL + l0 + c * 128 + l)) * DD + hh * 64);
            float acc = 0.f;
#pragma unroll 4
            for (int i = 0; i < 16; i++) {
                float4 k4 = kp[i];
                float4 x = make_float4(k4.x * SCALE, k4.y * SCALE, k4.z * SCALE, k4.w * SCALE);
                acc = fmaf(x.x, x.x, fmaf(x.y, x.y, fmaf(x.z, x.z, fmaf(x.w, x.w, acc))));
                split4u(sm + SB_KHI + l * 144 + i * 8, sm + SB_KLO + l * 144 + i * 8, x);
            }
            h_s[l] = -0.5f * acc;
        } else {
            int l = tid - 128;
            const float4* vp = (const float4*)(Vt + ((size_t)(b * LL + l0 + c * 128 + l)) * DD + hh * 64);
#pragma unroll 4
            for (int i = 0; i < 16; i++)
                split4u(sm + SB_VHI + l * 144 + i * 8, sm + SB_VLO + l * 144 + i * 8, vp[i]);
        }
        __syncthreads();

        for (int lh = 0; lh < 2; lh++) {
            /* ---- GEMM1: proj[64 l][256 m], warp = 16 l x 64 m, 2 m-iters ---- */
            const int lgrp = w >> 1, mg = w & 1;
            const int lw = lh * 64 + lgrp * 16;
            const uint32_t aRowOff = (uint32_t)(lw + (lane & 15)) * 144 + (lane >> 4) * 16;
#pragma unroll
            for (int t = 0; t < 2; t++) {
                const int mbase = mg * 64 + t * 128;
                float D1[8][4];
#pragma unroll
                for (int j = 0; j < 8; j++)
#pragma unroll
                    for (int e = 0; e < 4; e++) D1[j][e] = 0.f;
                const uint32_t bRowOff =
                    (uint32_t)(mbase + (lane & 7) + ((lane >> 4) << 3)) * 144 + ((lane >> 3) & 1) * 16;
#pragma unroll
                for (int ks = 0; ks < 4; ks++) {
                    uint32_t aH[4], aL[4];
                    ldsm4(aH, s + SB_KHI + aRowOff + ks * 32);
                    ldsm4(aL, s + SB_KLO + aRowOff + ks * 32);
#pragma unroll
                    for (int nt = 0; nt < 4; nt++) {
                        uint32_t bH[4], bL[4];
                        ldsm4(bH, s + SB_WHI + bRowOff + nt * 16 * 144 + ks * 32);
                        ldsm4(bL, s + SB_WLO + bRowOff + nt * 16 * 144 + ks * 32);
                        mmabf(D1[nt * 2], aH, bH); mmabf(D1[nt * 2 + 1], aH, bH + 2);
                        mmabf(D1[nt * 2], aL, bH); mmabf(D1[nt * 2 + 1], aL, bH + 2);
                        mmabf(D1[nt * 2], aH, bL); mmabf(D1[nt * 2 + 1], aH, bL + 2);
                    }
                }
                /* epilogue: exp -> k' hi/lo [local l][m] */
                const float hb0 = h_s[lw + r] - stab;
                const float hb1 = h_s[lw + r + 8] - stab;
                const int lr0 = lgrp * 16 + r;
#pragma unroll
                for (int j = 0; j < 8; j++) {
                    int n = mbase + j * 8 + 2 * q;
                    float e00 = fmaf(CF, fexp(hb0 + D1[j][0]), CEPS);
                    float e01 = fmaf(CF, fexp(hb0 + D1[j][1]), CEPS);
                    float e10 = fmaf(CF, fexp(hb1 + D1[j][2]), CEPS);
                    float e11 = fmaf(CF, fexp(hb1 + D1[j][3]), CEPS);
                    *(uint32_t*)(sm + SB_KPH + lr0 * 528 + n * 2) = pk2(e00, e01);
                    *(uint32_t*)(sm + SB_KPH + (lr0 + 8) * 528 + n * 2) = pk2(e10, e11);
                    *(uint32_t*)(sm + SB_KPL + lr0 * 528 + n * 2) =
                        pk2(e00 - bhi_f(e00), e01 - bhi_f(e01));
                    *(uint32_t*)(sm + SB_KPL + (lr0 + 8) * 528 + n * 2) =
                        pk2(e10 - bhi_f(e10), e11 - bhi_f(e11));
                }
            }
            __syncthreads();

            /* ---- GEMM2: kv[256 m][72] += k'^T @ [v|1], K=64 ---- */
#pragma unroll
            for (int mg2 = 0; mg2 < 2; mg2++) {
                const int m0 = mg2 * 128 + w * 16;
                const uint32_t aR = (lane & 7) + ((lane >> 4) & 1) * 8;
                const uint32_t aC = (uint32_t)(m0 + ((lane >> 3) & 1) * 8) * 2;
                const uint32_t bR = (lane & 7) + ((lane >> 3) & 1) * 8;
                const uint32_t bC = ((lane >> 4) << 3) * 2;
#pragma unroll
                for (int ks = 0; ks < 4; ks++) {
                    uint32_t aH[4], aL[4];
                    ldsm4t(aH, s + SB_KPH + (ks * 16 + aR) * 528 + aC);
                    ldsm4t(aL, s + SB_KPL + (ks * 16 + aR) * 528 + aC);
                    const uint32_t vrow = (uint32_t)(lh * 64 + ks * 16 + bR) * 144;
#pragma unroll
                    for (int nt = 0; nt < 4; nt++) {
                        uint32_t bH[4], bL[4];
                        ldsm4t(bH, s + SB_VHI + vrow + nt * 32 + bC);
                        ldsm4t(bL, s + SB_VLO + vrow + nt * 32 + bC);
                        mmabf(D2[mg2][nt * 2], aH, bH); mmabf(D2[mg2][nt * 2 + 1], aH, bH + 2);
                        mmabf(D2[mg2][nt * 2], aL, bH); mmabf(D2[mg2][nt * 2 + 1], aL, bH + 2);
                        mmabf(D2[mg2][nt * 2], aH, bL); mmabf(D2[mg2][nt * 2 + 1], aH, bL + 2);
                    }
                    {   /* ntile 8: ones column (hi only; lo is zero) */
                        uint32_t bH[2];
                        ldsm2t(bH, s + SB_VHI + vrow + 128);
                        mmabf(D2[mg2][8], aH, bH);
                        mmabf(D2[mg2][8], aL, bH);
                    }
                }
            }
            __syncthreads();
        }
    }

    /* accumulate to gmem */
    float* kvg = g_kv + (size_t)bh * 72 * 256;
#pragma unroll
    for (int mg2 = 0; mg2 < 2; mg2++) {
        int m = mg2 * 128 + w * 16 + r;
#pragma unroll
        for (int j = 0; j < 8; j++) {
            int d = j * 8 + 2 * q;
            atomicAdd(&kvg[d * 256 + m],           D2[mg2][j][0]);
            atomicAdd(&kvg[(d + 1) * 256 + m],     D2[mg2][j][1]);
            atomicAdd(&kvg[d * 256 + m + 8],       D2[mg2][j][2]);
            atomicAdd(&kvg[(d + 1) * 256 + m + 8], D2[mg2][j][3]);
        }
        if (q == 0) {
            atomicAdd(&kvg[64 * 256 + m],     D2[mg2][8][0]);
            atomicAdd(&kvg[64 * 256 + m + 8], D2[mg2][8][2]);
        }
    }
}

/* ---------------- Kernel C: out = (q' @ [kv|ksum]) / den ----------------- */
__global__ void __launch_bounds__(256, 1)
k_out(const float* __restrict__ Qt, const float* __restrict__ Wt,
      float* __restrict__ Out) {
    extern __shared__ char sm[];
    const uint32_t s = smem_u32(sm);
    const int tid = threadIdx.x, lane = tid & 31, w = tid >> 5;
    const int bh = blockIdx.x >> 5, lc = blockIdx.x & 31;
    const int b = bh >> 4, hh = bh & 15;
    const int l0 = lc * 128;
    const int q = lane & 3, r = lane >> 2;

    for (int i = tid; i < 4096; i += 256) {
        int m = i >> 4, cb = (i & 15) * 8;
        split4u(sm + SC_WHI + m * 144 + cb, sm + SC_WLO + m * 144 + cb,
                ((const float4*)Wt)[i]);
    }
    for (int i = tid; i < 2048; i += 256) {
        int l = i >> 4, cb = (i & 15) * 8;
        const float4* qp = (const float4*)(Qt + ((size_t)(b * LL + l0 + l)) * DD + hh * 64);
        float4 q4 = qp[i & 15];
        float4 x = make_float4(q4.x * SCALE, q4.y * SCALE, q4.z * SCALE, q4.w * SCALE);
        split4u(sm + SC_QHI + l * 144 + cb, sm + SC_QLO + l * 144 + cb, x);
    }
    __syncthreads();

    float D2[9][4];
#pragma unroll
    for (int j = 0; j < 9; j++)
#pragma unroll
        for (int e = 0; e < 4; e++) D2[j][e] = 0.f;

    const int lw = w * 16;
    const uint32_t aRowOff = (uint32_t)(lw + (lane & 15)) * 144 + (lane >> 4) * 16;

    for (int c = 0; c < 2; c++) {
        /* stage kv chunk [72][128 m] hi/lo */
        {
            const float* kvg = g_kv + (size_t)bh * 72 * 256 + c * 128;
            for (int i = tid; i < 2304; i += 256) {
                int d = i >> 5, c4 = (i & 31) * 4;
                float4 v = *(const float4*)(kvg + d * 256 + c4);
                split4u(sm + SC_KVH + d * 272 + c4 * 2, sm + SC_KVL + d * 272 + c4 * 2, v);
            }
        }
        /* GEMM1: proj[128 l][128 m-half], warp = 16 l x 128 m */
        float D1[16][4];
#pragma unroll
        for (int j = 0; j < 16; j++)
#pragma unroll
            for (int e = 0; e < 4; e++) D1[j][e] = 0.f;
        const uint32_t bRowOff =
            (uint32_t)(c * 128 + (lane & 7) + ((lane >> 4) << 3)) * 144 + ((lane >> 3) & 1) * 16;
#pragma unroll
        for (int ks = 0; ks < 4; ks++) {
            uint32_t aH[4], aL[4];
            ldsm4(aH, s + SC_QHI + aRowOff + ks * 32);
            ldsm4(aL, s + SC_QLO + aRowOff + ks * 32);
#pragma unroll
            for (int nt = 0; nt < 8; nt++) {
                uint32_t bH[4], bL[4];
                ldsm4(bH, s + SC_WHI + bRowOff + nt * 16 * 144 + ks * 32);
                ldsm4(bL, s + SC_WLO + bRowOff + nt * 16 * 144 + ks * 32);
                mmabf(D1[nt * 2], aH, bH); mmabf(D1[nt * 2 + 1], aH, bH + 2);
                mmabf(D1[nt * 2], aL, bH); mmabf(D1[nt * 2 + 1], aL, bH + 2);
                mmabf(D1[nt * 2], aH, bL); mmabf(D1[nt * 2 + 1], aH, bL + 2);
            }
        }
        /* epilogue: q' = CF*exp(proj)+CEPS -> [l][m-local] hi/lo */
#pragma unroll
        for (int j = 0; j < 16; j++) {
            int ml = j * 8 + 2 * q;
            float e00 = fmaf(CF, fexp(D1[j][0]), CEPS);
            float e01 = fmaf(CF, fexp(D1[j][1]), CEPS);
            float e10 = fmaf(CF, fexp(D1[j][2]), CEPS);
            float e11 = fmaf(CF, fexp(D1[j][3]), CEPS);
            *(uint32_t*)(sm + SC_QPH + (lw + r) * 272 + ml * 2) = pk2(e00, e01);
            *(uint32_t*)(sm + SC_QPH + (lw + r + 8) * 272 + ml * 2) = pk2(e10, e11);
            *(uint32_t*)(sm + SC_QPL + (lw + r) * 272 + ml * 2) =
                pk2(e00 - bhi_f(e00), e01 - bhi_f(e01));
            *(uint32_t*)(sm + SC_QPL + (lw + r + 8) * 272 + ml * 2) =
                pk2(e10 - bhi_f(e10), e11 - bhi_f(e11));
        }
        __syncthreads();

        /* GEMM2: out[128 l][72] += q'_chunk @ kv_chunk^T, K=128 */
        const uint32_t a2Off = (uint32_t)(lw + (lane & 15)) * 272 + (lane >> 4) * 16;
        const uint32_t b2RowPart = (lane & 7) + ((lane >> 4) << 3);
        const uint32_t b2ColPart = ((lane >> 3) & 1) * 16;
#pragma unroll
        for (int ks = 0; ks < 8; ks++) {
            uint32_t aH[4], aL[4];
            ldsm4(aH, s + SC_QPH + a2Off + ks * 32);
            ldsm4(aL, s + SC_QPL + a2Off + ks * 32);
#pragma unroll
            for (int nt = 0; nt < 4; nt++) {
                uint32_t bH[4], bL[4];
                uint32_t boff = (nt * 16 + b2RowPart) * 272 + b2ColPart + ks * 32;
                ldsm4(bH, s + SC_KVH + boff);
                ldsm4(bL, s + SC_KVL + boff);
                mmabf(D2[nt * 2], aH, bH); mmabf(D2[nt * 2 + 1], aH, bH + 2);
                mmabf(D2[nt * 2], aL, bH); mmabf(D2[nt * 2 + 1], aL, bH + 2);
                mmabf(D2[nt * 2], aH, bL); mmabf(D2[nt * 2 + 1], aH, bL + 2);
            }
            {   /* ntile 8 (ksum row + zero pad rows) */
                uint32_t bH[2], bL[2];
                uint32_t boff = (64 + (lane & 7)) * 272 + b2ColPart + ks * 32;
                ldsm2(bH, s + SC_KVH + boff);
                ldsm2(bL, s + SC_KVL + boff);
                mmabf(D2[8], aH, bH);
                mmabf(D2[8], aL, bH);
                mmabf(D2[8], aH, bL);
            }
        }
        __syncthreads();
    }

    /* divide by denominator (col 64) and store */
    float den0 = __shfl_sync(0xffffffffu, D2[8][0], lane & ~3);
    float den1 = __shfl_sync(0xffffffffu, D2[8][2], lane & ~3);
    if (fabsf(den0) <= EPSV) den0 += 2.f * EPSV;
    if (fabsf(den1) <= EPSV) den1 += 2.f * EPSV;
    float inv0 = 1.0f / den0, inv1 = 1.0f / den1;
    float* O0 = Out + ((size_t)(b * LL + l0 + lw + r)) * DD + hh * 64;
    float* O1 = Out + ((size_t)(b * LL + l0 + lw + r + 8)) * DD + hh * 64;
#pragma unroll
    for (int j = 0; j < 8; j++) {
        int d = j * 8 + 2 * q;
        *(float2*)(O0 + d) = make_float2(D2[j][0] * inv0, D2[j][1] * inv0);
        *(float2*)(O1 + d) = make_float2(D2[j][2] * inv1, D2[j][3] * inv1);
    }
}

extern "C" void kernel_launch(void* const* d_in, const int* in_sizes, int n_in,
                              void* d_out, int out_size) {
    const float* q = (const float*)d_in[0];
    const float* k = (const float*)d_in[1];
    const float* v = (const float*)d_in[2];
    const float* W = (const float*)d_in[3];
    float* out = (float*)d_out;

    void *pkv, *pmin;
    cudaGetSymbolAddress(&pkv, g_kv);
    cudaGetSymbolAddress(&pmin, g_minbits);
    cudaMemsetAsync(pkv, 0, sizeof(float) * BB * HH * 72 * 256, 0);
    cudaMemsetAsync(pmin, 0x7F, 4, 0);

    cudaFuncSetAttribute(k_kv, cudaFuncAttributeMaxDynamicSharedMemorySize, SB_SMEM);
    cudaFuncSetAttribute(k_out, cudaFuncAttributeMaxDynamicSharedMemorySize, SC_SMEM);

    k_minsq<<<(BB * LL * HH) / 256, 256>>>(k);
    k_kv<<<BB * HH * 8, 256, SB_SMEM>>>(k, v, W);
    k_out<<<BB * HH * 32, 256, SC_SMEM>>>(q, W, out);
}

// round 7
// speedup vs baseline: 3.6547x; 1.0682x over previous
#include <cuda_runtime.h>
#include <cuda_bf16.h>
#include <cstdint>

#define BB 4
#define LL 4096
#define DD 1024
#define HH 16
#define MM 256

#define SCALE 0.17677669529663689f   /* 1024^-0.25 */
#define CF    0.0625f                /* 256^-0.5   */
#define EPSV  1e-4f
#define CEPS  (0.0625f*1e-4f)

__device__ float    g_kv[BB*HH*72*256];   /* [bh][d(0..63)|ksum(64)|pad][m] */
__device__ unsigned g_minbits;

/* ---- k_kv smem map (bytes); row stride 144B (=128+16, ldsm conflict-free) */
#define SB_H    0          /* 128 floats */
#define SB_WHI  512        /* W  [256 m][64 k] -> 36864 */
#define SB_WLO  37376
#define SB_KHI  74240      /* k  [128 l][64 k] -> 18432 */
#define SB_KLO  92672
#define SB_VHI  111104     /* v  [128 l][72 d] -> 18432 */
#define SB_VLO  129536
#define SB_SMEM 147968

/* ---- k_out smem map; kv stride 272B ---- */
#define SC_WHI  0          /* 36864 */
#define SC_WLO  36864
#define SC_QHI  73728      /* [128 l][64 k] -> 18432 */
#define SC_QLO  92160
#define SC_KVH  110592     /* kv [72 d][128 m] stride 272 -> 19584 */
#define SC_KVL  130176
#define SC_SMEM 149760

/* ------------------------------- helpers -------------------------------- */
__device__ __forceinline__ uint32_t smem_u32(const void* p) {
    uint32_t a;
    asm("{ .reg .u64 t; cvta.to.shared.u64 t, %1; cvt.u32.u64 %0, t; }" : "=r"(a) : "l"(p));
    return a;
}
__device__ __forceinline__ void ldsm4(uint32_t* r, uint32_t a) {
    asm volatile("ldmatrix.sync.aligned.m8n8.x4.shared.b16 {%0,%1,%2,%3}, [%4];"
                 : "=r"(r[0]), "=r"(r[1]), "=r"(r[2]), "=r"(r[3]) : "r"(a));
}
__device__ __forceinline__ void ldsm4t(uint32_t* r, uint32_t a) {
    asm volatile("ldmatrix.sync.aligned.m8n8.x4.trans.shared.b16 {%0,%1,%2,%3}, [%4];"
                 : "=r"(r[0]), "=r"(r[1]), "=r"(r[2]), "=r"(r[3]) : "r"(a));
}
__device__ __forceinline__ void ldsm2(uint32_t* r, uint32_t a) {
    asm volatile("ldmatrix.sync.aligned.m8n8.x2.shared.b16 {%0,%1}, [%2];"
                 : "=r"(r[0]), "=r"(r[1]) : "r"(a));
}
__device__ __forceinline__ void ldsm2t(uint32_t* r, uint32_t a) {
    asm volatile("ldmatrix.sync.aligned.m8n8.x2.trans.shared.b16 {%0,%1}, [%2];"
                 : "=r"(r[0]), "=r"(r[1]) : "r"(a));
}
__device__ __forceinline__ void mmabf(float* d, const uint32_t* a, const uint32_t* b) {
    asm volatile("mma.sync.aligned.m16n8k16.row.col.f32.bf16.bf16.f32 "
                 "{%0,%1,%2,%3},{%4,%5,%6,%7},{%8,%9},{%0,%1,%2,%3};"
                 : "+f"(d[0]), "+f"(d[1]), "+f"(d[2]), "+f"(d[3])
                 : "r"(a[0]), "r"(a[1]), "r"(a[2]), "r"(a[3]), "r"(b[0]), "r"(b[1]));
}
__device__ __forceinline__ float fexp(float x) {
    float t = x * 1.4426950408889634f;
    t = fminf(fmaxf(t, -126.0f), 126.0f);
    float z = t + 12582912.0f;
    int   n = __float_as_int(z) - 0x4B400000;
    float f = t - (float)n;
    float p = 1.54035304e-4f;
    p = fmaf(p, f, 1.33335581e-3f);
    p = fmaf(p, f, 9.61812911e-3f);
    p = fmaf(p, f, 5.55041087e-2f);
    p = fmaf(p, f, 2.40226507e-1f);
    p = fmaf(p, f, 6.93147181e-1f);
    p = fmaf(p, f, 1.0f);
    return __int_as_float((n + 127) << 23) * p;
}
__device__ __forceinline__ float bhi_f(float x) {
    return __bfloat162float(__float2bfloat16_rn(x));
}
__device__ __forceinline__ uint32_t pk2(float a, float b) {
    __nv_bfloat162 h = __floats2bfloat162_rn(a, b);
    return *(uint32_t*)&h;
}
__device__ __forceinline__ void split4u(char* hi, char* lo, float4 w) {
    float hx = bhi_f(w.x), hy = bhi_f(w.y), hz = bhi_f(w.z), hw = bhi_f(w.w);
    *(uint2*)hi = make_uint2(pk2(hx, hy), pk2(hz, hw));
    *(uint2*)lo = make_uint2(pk2(w.x - hx, w.y - hy), pk2(w.z - hz, w.w - hw));
}
/* D-frag quad (2 adjacent n8 tiles) -> A-frag (hi + lo), after f(x) applied */
__device__ __forceinline__ void dfrag_to_afrag(const float* e0, const float* e1,
                                               uint32_t* aH, uint32_t* aL) {
    aH[0] = pk2(e0[0], e0[1]); aH[1] = pk2(e0[2], e0[3]);
    aH[2] = pk2(e1[0], e1[1]); aH[3] = pk2(e1[2], e1[3]);
    aL[0] = pk2(e0[0] - bhi_f(e0[0]), e0[1] - bhi_f(e0[1]));
    aL[1] = pk2(e0[2] - bhi_f(e0[2]), e0[3] - bhi_f(e0[3]));
    aL[2] = pk2(e1[0] - bhi_f(e1[0]), e1[1] - bhi_f(e1[1]));
    aL[3] = pk2(e1[2] - bhi_f(e1[2]), e1[3] - bhi_f(e1[3]));
}

/* ---------------- Kernel 1: global min ||k_scaled||^2 -------------------- */
__global__ void __launch_bounds__(256) k_minsq(const float* __restrict__ Kt) {
    int idx = blockIdx.x * 256 + threadIdx.x;   /* half head-row (32 floats) */
    const float4* p = (const float4*)Kt + (size_t)idx * 8;
    float s = 0.f;
#pragma unroll
    for (int i = 0; i < 8; i++) {
        float4 v = p[i];
        s = fmaf(v.x, v.x, s); s = fmaf(v.y, v.y, s);
        s = fmaf(v.z, v.z, s); s = fmaf(v.w, v.w, s);
    }
    s *= SCALE * SCALE;
    s += __shfl_xor_sync(0xffffffffu, s, 1);   /* pair = full row */
#pragma unroll
    for (int o = 16; o > 1; o >>= 1) s = fminf(s, __shfl_xor_sync(0xffffffffu, s, o));
    if ((threadIdx.x & 31) == 0) atomicMin(&g_minbits, __float_as_uint(s));
}

/* ---------------- Kernel B: k'=phi(k); kv += k'^T [v|1] ------------------ */
/* GEMM1 transposed: D1'[m][l] = W @ k^T, so D1' frags convert directly to
   GEMM2 A-frags (A = k'^T rows = m). */
__global__ void __launch_bounds__(256, 1)
k_kv(const float* __restrict__ Kt, const float* __restrict__ Vt,
     const float* __restrict__ Wt) {
    extern __shared__ char sm[];
    const uint32_t s = smem_u32(sm);
    float* h_s = (float*)sm;
    const int tid = threadIdx.x, lane = tid & 31, w = tid >> 5;
    const int bh = blockIdx.x >> 4, spl = blockIdx.x & 15;
    const int b = bh >> 4, hh = bh & 15;
    const int l0 = spl * 256;
    const float stab = -0.5f * __uint_as_float(g_minbits);
    const int q = lane & 3, r = lane >> 2;

    /* stage W hi/lo [m][k] */
    for (int i = tid; i < 4096; i += 256) {
        int m = i >> 4, cb = (i & 15) * 8;
        split4u(sm + SB_WHI + m * 144 + cb, sm + SB_WLO + m * 144 + cb,
                ((const float4*)Wt)[i]);
    }
    /* v cols 64..71: ones + pad (persist across chunks) */
    for (int i = tid; i < 1024; i += 256) {
        int l = i >> 3, cc = 64 + (i & 7);
        *(uint16_t*)(sm + SB_VHI + l * 144 + cc * 2) = (cc == 64) ? 0x3F80 : 0;
        *(uint16_t*)(sm + SB_VLO + l * 144 + cc * 2) = 0;
    }

    float D2[2][9][4];
#pragma unroll
    for (int a = 0; a < 2; a++)
#pragma unroll
        for (int j = 0; j < 9; j++)
#pragma unroll
            for (int e = 0; e < 4; e++) D2[a][j][e] = 0.f;

    /* per-warp operand bases */
    const uint32_t aHB = s + SB_WHI + (uint32_t)(w * 32 + (lane & 15)) * 144 + (lane >> 4) * 16;
    const uint32_t aLB = s + SB_WLO + (uint32_t)(w * 32 + (lane & 15)) * 144 + (lane >> 4) * 16;
    const uint32_t bRow = (lane & 7) + ((lane >> 4) << 3);
    const uint32_t bCol = ((lane >> 3) & 1) * 16;
    const uint32_t vRow = (lane & 7) + ((lane >> 3) & 1) * 8;
    const uint32_t vCol = ((lane >> 4) << 3) * 2;

    for (int c = 0; c < 2; c++) {
        __syncthreads();   /* staging buffers free (prev chunk's GEMMs done) */
        if (tid < 128) {
            int l = tid;
            const float4* kp = (const float4*)(Kt + ((size_t)(b * LL + l0 + c * 128 + l)) * DD + hh * 64);
            float acc = 0.f;
#pragma unroll 4
            for (int i = 0; i < 16; i++) {
                float4 k4 = kp[i];
                float4 x = make_float4(k4.x * SCALE, k4.y * SCALE, k4.z * SCALE, k4.w * SCALE);
                acc = fmaf(x.x, x.x, fmaf(x.y, x.y, fmaf(x.z, x.z, fmaf(x.w, x.w, acc))));
                split4u(sm + SB_KHI + l * 144 + i * 8, sm + SB_KLO + l * 144 + i * 8, x);
            }
            h_s[l] = -0.5f * acc;
        } else {
            int l = tid - 128;
            const float4* vp = (const float4*)(Vt + ((size_t)(b * LL + l0 + c * 128 + l)) * DD + hh * 64);
#pragma unroll 4
            for (int i = 0; i < 16; i++)
                split4u(sm + SB_VHI + l * 144 + i * 8, sm + SB_VLO + l * 144 + i * 8, vp[i]);
        }
        __syncthreads();

        for (int lh = 0; lh < 2; lh++) {
            /* ---- GEMM1': D1'[32 m][64 l] = W @ k^T ---- */
            float D1[2][8][4];
#pragma unroll
            for (int mt = 0; mt < 2; mt++)
#pragma unroll
                for (int j = 0; j < 8; j++)
#pragma unroll
                    for (int e = 0; e < 4; e++) D1[mt][j][e] = 0.f;
#pragma unroll
            for (int ks = 0; ks < 4; ks++) {
                uint32_t aH[2][4], aL[2][4];
                ldsm4(aH[0], aHB + ks * 32);
                ldsm4(aH[1], aHB + 16 * 144 + ks * 32);
                ldsm4(aL[0], aLB + ks * 32);
                ldsm4(aL[1], aLB + 16 * 144 + ks * 32);
#pragma unroll
                for (int nt = 0; nt < 4; nt++) {
                    uint32_t bH[4], bL[4];
                    uint32_t bo = (uint32_t)(lh * 64 + nt * 16 + bRow) * 144 + bCol + ks * 32;
                    ldsm4(bH, s + SB_KHI + bo);
                    ldsm4(bL, s + SB_KLO + bo);
#pragma unroll
                    for (int mt = 0; mt < 2; mt++) {
                        mmabf(D1[mt][nt * 2], aH[mt], bH); mmabf(D1[mt][nt * 2 + 1], aH[mt], bH + 2);
                        mmabf(D1[mt][nt * 2], aL[mt], bH); mmabf(D1[mt][nt * 2 + 1], aL[mt], bH + 2);
                        mmabf(D1[mt][nt * 2], aH[mt], bL); mmabf(D1[mt][nt * 2 + 1], aH[mt], bL + 2);
                    }
                }
            }
            /* ---- epilogue in registers: k' = CF*exp(h + proj - stab)+CEPS,
                   D-frags -> GEMM2 A-frags ---- */
            uint32_t A2H[2][4][4], A2L[2][4][4];
#pragma unroll
            for (int t = 0; t < 4; t++) {
                float hA0 = h_s[lh * 64 + 16 * t + 2 * q] + stab;
                float hB0 = h_s[lh * 64 + 16 * t + 2 * q + 1] + stab;
                float hA1 = h_s[lh * 64 + 16 * t + 8 + 2 * q] + stab;
                float hB1 = h_s[lh * 64 + 16 * t + 8 + 2 * q + 1] + stab;
#pragma unroll
                for (int mt = 0; mt < 2; mt++) {
                    float e0[4], e1[4];
                    e0[0] = fmaf(CF, fexp(hA0 + D1[mt][2 * t][0]), CEPS);
                    e0[1] = fmaf(CF, fexp(hB0 + D1[mt][2 * t][1]), CEPS);
                    e0[2] = fmaf(CF, fexp(hA0 + D1[mt][2 * t][2]), CEPS);
                    e0[3] = fmaf(CF, fexp(hB0 + D1[mt][2 * t][3]), CEPS);
                    e1[0] = fmaf(CF, fexp(hA1 + D1[mt][2 * t + 1][0]), CEPS);
                    e1[1] = fmaf(CF, fexp(hB1 + D1[mt][2 * t + 1][1]), CEPS);
                    e1[2] = fmaf(CF, fexp(hA1 + D1[mt][2 * t + 1][2]), CEPS);
                    e1[3] = fmaf(CF, fexp(hB1 + D1[mt][2 * t + 1][3]), CEPS);
                    dfrag_to_afrag(e0, e1, A2H[mt][t], A2L[mt][t]);
                }
            }
            /* ---- GEMM2: kv[32 m][72] += k'^T_half @ [v|1]_half ---- */
#pragma unroll
            for (int ks = 0; ks < 4; ks++) {
                uint32_t vb = (uint32_t)(lh * 64 + ks * 16 + vRow) * 144 + vCol;
#pragma unroll
                for (int nt = 0; nt < 4; nt++) {
                    uint32_t bH[4], bL[4];
                    ldsm4t(bH, s + SB_VHI + vb + nt * 32);
                    ldsm4t(bL, s + SB_VLO + vb + nt * 32);
#pragma unroll
                    for (int mt = 0; mt < 2; mt++) {
                        mmabf(D2[mt][nt * 2], A2H[mt][ks], bH); mmabf(D2[mt][nt * 2 + 1], A2H[mt][ks], bH + 2);
                        mmabf(D2[mt][nt * 2], A2L[mt][ks], bH); mmabf(D2[mt][nt * 2 + 1], A2L[mt][ks], bH + 2);
                        mmabf(D2[mt][nt * 2], A2H[mt][ks], bL); mmabf(D2[mt][nt * 2 + 1], A2H[mt][ks], bL + 2);
                    }
                }
                {   /* ones column tile (cols 64..71); Blo = 0 */
                    uint32_t b1[2];
                    ldsm2t(b1, s + SB_VHI + vb + 128);
#pragma unroll
                    for (int mt = 0; mt < 2; mt++) {
                        mmabf(D2[mt][8], A2H[mt][ks], b1);
                        mmabf(D2[mt][8], A2L[mt][ks], b1);
                    }
                }
            }
        }
    }

    float* kvg = g_kv + (size_t)bh * 72 * 256;
#pragma unroll
    for (int mt = 0; mt < 2; mt++) {
        int m = w * 32 + mt * 16 + r;
#pragma unroll
        for (int j = 0; j < 8; j++) {
            int d = j * 8 + 2 * q;
            atomicAdd(&kvg[d * 256 + m],           D2[mt][j][0]);
            atomicAdd(&kvg[(d + 1) * 256 + m],     D2[mt][j][1]);
            atomicAdd(&kvg[d * 256 + m + 8],       D2[mt][j][2]);
            atomicAdd(&kvg[(d + 1) * 256 + m + 8], D2[mt][j][3]);
        }
        if (q == 0) {
            atomicAdd(&kvg[64 * 256 + m],     D2[mt][8][0]);
            atomicAdd(&kvg[64 * 256 + m + 8], D2[mt][8][2]);
        }
    }
}

/* ---------------- Kernel C: out = (q' @ [kv|ksum]) / den ----------------- */
__global__ void __launch_bounds__(256, 1)
k_out(const float* __restrict__ Qt, const float* __restrict__ Wt,
      float* __restrict__ Out) {
    extern __shared__ char sm[];
    const uint32_t s = smem_u32(sm);
    const int tid = threadIdx.x, lane = tid & 31, w = tid >> 5;
    const int bh = blockIdx.x >> 5, lc = blockIdx.x & 31;
    const int b = bh >> 4, hh = bh & 15;
    const int l0 = lc * 128;
    const int q = lane & 3, r = lane >> 2;

    for (int i = tid; i < 4096; i += 256) {
        int m = i >> 4, cb = (i & 15) * 8;
        split4u(sm + SC_WHI + m * 144 + cb, sm + SC_WLO + m * 144 + cb,
                ((const float4*)Wt)[i]);
    }
    for (int i = tid; i < 2048; i += 256) {
        int l = i >> 4, cb = (i & 15) * 8;
        const float4* qp = (const float4*)(Qt + ((size_t)(b * LL + l0 + l)) * DD + hh * 64);
        float4 q4 = qp[i & 15];
        float4 x = make_float4(q4.x * SCALE, q4.y * SCALE, q4.z * SCALE, q4.w * SCALE);
        split4u(sm + SC_QHI + l * 144 + cb, sm + SC_QLO + l * 144 + cb, x);
    }

    float D2[9][4];
#pragma unroll
    for (int j = 0; j < 9; j++)
#pragma unroll
        for (int e = 0; e < 4; e++) D2[j][e] = 0.f;

    const int lw = w * 16;
    const uint32_t aHB = s + SC_QHI + (uint32_t)(lw + (lane & 15)) * 144 + (lane >> 4) * 16;
    const uint32_t aLB = s + SC_QLO + (uint32_t)(lw + (lane & 15)) * 144 + (lane >> 4) * 16;
    const uint32_t bRow = (lane & 7) + ((lane >> 4) << 3);
    const uint32_t bCol = ((lane >> 3) & 1) * 16;

    for (int c = 0; c < 2; c++) {
        __syncthreads();   /* KV buffers free / q,W staged (first iter) */
        {
            const float* kvg = g_kv + (size_t)bh * 72 * 256 + c * 128;
            for (int i = tid; i < 2304; i += 256) {
                int d = i >> 5, c4 = (i & 31) * 4;
                float4 v = *(const float4*)(kvg + d * 256 + c4);
                split4u(sm + SC_KVH + d * 272 + c4 * 2, sm + SC_KVL + d * 272 + c4 * 2, v);
            }
        }
        __syncthreads();

        /* GEMM1: proj[16 l][128 m-half] */
        float D1[16][4];
#pragma unroll
        for (int j = 0; j < 16; j++)
#pragma unroll
            for (int e = 0; e < 4; e++) D1[j][e] = 0.f;
#pragma unroll
        for (int ks = 0; ks < 4; ks++) {
            uint32_t aH[4], aL[4];
            ldsm4(aH, aHB + ks * 32);
            ldsm4(aL, aLB + ks * 32);
#pragma unroll
            for (int nt = 0; nt < 8; nt++) {
                uint32_t bH[4], bL[4];
                uint32_t bo = (uint32_t)(c * 128 + nt * 16 + bRow) * 144 + bCol + ks * 32;
                ldsm4(bH, s + SC_WHI + bo);
                ldsm4(bL, s + SC_WLO + bo);
                mmabf(D1[nt * 2], aH, bH); mmabf(D1[nt * 2 + 1], aH, bH + 2);
                mmabf(D1[nt * 2], aL, bH); mmabf(D1[nt * 2 + 1], aL, bH + 2);
                mmabf(D1[nt * 2], aH, bL); mmabf(D1[nt * 2 + 1], aH, bL + 2);
            }
        }
        /* epilogue in registers: q' = CF*exp(proj)+CEPS -> A-frags (K=128) */
        uint32_t A2H[8][4], A2L[8][4];
#pragma unroll
        for (int t = 0; t < 8; t++) {
            float e0[4], e1[4];
#pragma unroll
            for (int e = 0; e < 4; e++) {
                e0[e] = fmaf(CF, fexp(D1[2 * t][e]), CEPS);
                e1[e] = fmaf(CF, fexp(D1[2 * t + 1][e]), CEPS);
            }
            dfrag_to_afrag(e0, e1, A2H[t], A2L[t]);
        }
        /* GEMM2: out[16 l][72] += q'_chunk @ kv_chunk^T */
#pragma unroll
        for (int ks = 0; ks < 8; ks++) {
#pragma unroll
            for (int nt = 0; nt < 4; nt++) {
                uint32_t bH[4], bL[4];
                uint32_t bo = (uint32_t)(nt * 16 + bRow) * 272 + bCol + ks * 32;
                ldsm4(bH, s + SC_KVH + bo);
                ldsm4(bL, s + SC_KVL + bo);
                mmabf(D2[nt * 2], A2H[ks], bH); mmabf(D2[nt * 2 + 1], A2H[ks], bH + 2);
                mmabf(D2[nt * 2], A2L[ks], bH); mmabf(D2[nt * 2 + 1], A2L[ks], bH + 2);
                mmabf(D2[nt * 2], A2H[ks], bL); mmabf(D2[nt * 2 + 1], A2H[ks], bL + 2);
            }
            {   /* ksum row tile (cols 64..71 of out) */
                uint32_t bH[2], bL[2];
                uint32_t bo = (uint32_t)(64 + (lane & 7)) * 272 + bCol + ks * 32;
                ldsm2(bH, s + SC_KVH + bo);
                ldsm2(bL, s + SC_KVL + bo);
                mmabf(D2[8], A2H[ks], bH);
                mmabf(D2[8], A2L[ks], bH);
                mmabf(D2[8], A2H[ks], bL);
            }
        }
    }

    /* divide by denominator (col 64) and store */
    float den0 = __shfl_sync(0xffffffffu, D2[8][0], lane & ~3);
    float den1 = __shfl_sync(0xffffffffu, D2[8][2], lane & ~3);
    if (fabsf(den0) <= EPSV) den0 += 2.f * EPSV;
    if (fabsf(den1) <= EPSV) den1 += 2.f * EPSV;
    float inv0 = 1.0f / den0, inv1 = 1.0f / den1;
    float* O0 = Out + ((size_t)(b * LL + l0 + lw + r)) * DD + hh * 64;
    float* O1 = Out + ((size_t)(b * LL + l0 + lw + r + 8)) * DD + hh * 64;
#pragma unroll
    for (int j = 0; j < 8; j++) {
        int d = j * 8 + 2 * q;
        *(float2*)(O0 + d) = make_float2(D2[j][0] * inv0, D2[j][1] * inv0);
        *(float2*)(O1 + d) = make_float2(D2[j][2] * inv1, D2[j][3] * inv1);
    }
}

extern "C" void kernel_launch(void* const* d_in, const int* in_sizes, int n_in,
                              void* d_out, int out_size) {
    const float* q = (const float*)d_in[0];
    const float* k = (const float*)d_in[1];
    const float* v = (const float*)d_in[2];
    const float* W = (const float*)d_in[3];
    float* out = (float*)d_out;

    void *pkv, *pmin;
    cudaGetSymbolAddress(&pkv, g_kv);
    cudaGetSymbolAddress(&pmin, g_minbits);
    cudaMemsetAsync(pkv, 0, sizeof(float) * BB * HH * 72 * 256, 0);
    cudaMemsetAsync(pmin, 0x7F, 4, 0);

    cudaFuncSetAttribute(k_kv, cudaFuncAttributeMaxDynamicSharedMemorySize, SB_SMEM);
    cudaFuncSetAttribute(k_out, cudaFuncAttributeMaxDynamicSharedMemorySize, SC_SMEM);

    k_minsq<<<(BB * LL * HH * 2) / 256, 256>>>(k);
    k_kv<<<BB * HH * 16, 256, SB_SMEM>>>(k, v, W);
    k_out<<<BB * HH * 32, 256, SC_SMEM>>>(q, W, out);
}